// round 14
// baseline (speedup 1.0000x reference)
#include <cuda_runtime.h>
#include <cuda_bf16.h>
#include <cstdint>

typedef unsigned long long ull;
#define FULL 0xffffffffu

constexpr int B_  = 16;
constexpr int N_  = 4096;
constexpr int NP_ = 1024;
constexpr int K_  = 32;
constexpr int CIN = 128;
constexpr int CG  = 131;   // 3 + 128
constexpr int C_  = 256;
constexpr int H_  = 4;
constexpr int D_  = 64;
constexpr int TC  = 768;   // 3*C
constexpr int G_  = 4;     // groups per attn block (M = 128 rows)
constexpr int GP  = 34;    // per-group sub-pitch (floats) in xsT row
constexpr int XP  = 138;   // xsT row pitch (floats)
constexpr int T_  = 512;   // attn threads
constexpr int KC  = 48;    // K-chunk for mma (AP=26 conflict-free pattern)
constexpr int AP  = 26;    // A/B smem row pitch in 32-bit words
constexpr int MR  = 32;    // mlp rows per block (2 m-tiles)
constexpr int MT_ = 512;   // mlp threads
constexpr int P1  = 154;   // lnPk pitch words (154 mod 32 == 26)
constexpr int P2  = 282;   // hPk pitch words  (282 mod 32 == 26)

// scratch (device globals: allocation-free rule; zero-initialized)
__device__ int   g_idx_buf[B_ * NP_ * K_];
__device__ float g_feat_buf[B_ * NP_ * C_];
// weights as bf16 hi/lo, PRE-PITCHED [chunk][part][n][26 words] (words 24,25 = 0)
__device__ __align__(16) unsigned g_wq[3 * 2 * 256 * 26];
__device__ __align__(16) unsigned g_w1[6 * 2 * 512 * 26];
__device__ __align__(16) unsigned g_w2[11 * 2 * 256 * 26];

extern __shared__ __align__(16) unsigned char dynsm[];

// ---------------- packed f32x2 helpers
__device__ __forceinline__ ull pk2(float a, float b) {
    ull r;
    asm("mov.b64 %0, {%1,%2};" : "=l"(r) : "f"(a), "f"(b));
    return r;
}
__device__ __forceinline__ void upk2(ull v, float& a, float& b) {
    asm("mov.b64 {%0,%1}, %2;" : "=f"(a), "=f"(b) : "l"(v));
}
__device__ __forceinline__ void fma2(ull& d, ull a, ull b) {
    asm("fma.rn.f32x2 %0, %1, %2, %3;" : "=l"(d) : "l"(a), "l"(b), "l"(d));
}

// ---------------- warp mma m16n8k16 bf16 (base PTX, works at compute_103)
__device__ __forceinline__ void mma16816(float* d, const unsigned* a, unsigned b0, unsigned b1) {
    asm volatile(
        "mma.sync.aligned.m16n8k16.row.col.f32.bf16.bf16.f32 "
        "{%0,%1,%2,%3}, {%4,%5,%6,%7}, {%8,%9}, {%0,%1,%2,%3};"
        : "+f"(d[0]), "+f"(d[1]), "+f"(d[2]), "+f"(d[3])
        : "r"(a[0]), "r"(a[1]), "r"(a[2]), "r"(a[3]), "r"(b0), "r"(b1));
}
__device__ __forceinline__ unsigned bf16pair(float x0, float x1) {
    const __nv_bfloat16 h0 = __float2bfloat16(x0), h1 = __float2bfloat16(x1);
    return (unsigned)__bfloat16_as_ushort(h0) | ((unsigned)__bfloat16_as_ushort(h1) << 16);
}
__device__ __forceinline__ unsigned smem_u32(const void* p) {
    unsigned a;
    asm("{ .reg .u64 t; cvta.to.shared.u64 t, %1; cvt.u32.u64 %0, t; }" : "=r"(a) : "l"(p));
    return a;
}
// ---------------- cp.async helpers (base PTX sm_80+)
__device__ __forceinline__ void cp16(unsigned smaddr, const void* gptr) {
    asm volatile("cp.async.cg.shared.global [%0], [%1], 16;" :: "r"(smaddr), "l"(gptr));
}
#define CP_COMMIT() asm volatile("cp.async.commit_group;" ::: "memory")
#define CP_WAIT1()  asm volatile("cp.async.wait_group 1;" ::: "memory")
#define CP_WAIT0()  asm volatile("cp.async.wait_group 0;" ::: "memory")

// monotone float -> uint map (order preserving)
__device__ __forceinline__ unsigned fmapu(float f) {
    unsigned u = __float_as_uint(f);
    return (u & 0x80000000u) ? ~u : (u | 0x80000000u);
}

// ============================================================================
// K0: prep — convert Wq, fc1w, fc2w to bf16 hi/lo pre-pitched layouts.
// ============================================================================
__global__ void __launch_bounds__(512) prep_kernel(const float* __restrict__ wqkv,
                                                   const float* __restrict__ fc1w,
                                                   const float* __restrict__ fc2w) {
    const int idx = blockIdx.x * 512 + threadIdx.x;
    if (idx < 18432) {                       // Wq: 3 chunks x 256 n x 24 j
        const int c = idx / 6144, rem = idx % 6144;
        const int n = rem / 24, j = rem % 24;
        const int k = c * KC + 2 * j;
        const float x0 = (k < CG) ? wqkv[(long)k * TC + n] : 0.f;
        const float x1 = (k + 1 < CG) ? wqkv[(long)(k + 1) * TC + n] : 0.f;
        const __nv_bfloat16 h0 = __float2bfloat16(x0), h1 = __float2bfloat16(x1);
        g_wq[(c * 2 + 0) * 6656 + n * 26 + j] = bf16pair(x0, x1);
        g_wq[(c * 2 + 1) * 6656 + n * 26 + j] =
            bf16pair(x0 - __bfloat162float(h0), x1 - __bfloat162float(h1));
    } else if (idx < 92160) {                // fc1w: 6 chunks x 512 n x 24 j
        const int i = idx - 18432;
        const int c = i / 12288, rem = i % 12288;
        const int n = rem / 24, j = rem % 24;
        const int k = c * KC + 2 * j;
        const float x0 = (k < C_) ? fc1w[(long)k * (2 * C_) + n] : 0.f;
        const float x1 = (k + 1 < C_) ? fc1w[(long)(k + 1) * (2 * C_) + n] : 0.f;
        const __nv_bfloat16 h0 = __float2bfloat16(x0), h1 = __float2bfloat16(x1);
        g_w1[(c * 2 + 0) * 13312 + n * 26 + j] = bf16pair(x0, x1);
        g_w1[(c * 2 + 1) * 13312 + n * 26 + j] =
            bf16pair(x0 - __bfloat162float(h0), x1 - __bfloat162float(h1));
    } else if (idx < 159744) {               // fc2w: 11 chunks x 256 n x 24 j
        const int i = idx - 92160;
        const int c = i / 6144, rem = i % 6144;
        const int n = rem / 24, j = rem % 24;
        const int k = c * KC + 2 * j;
        const float x0 = (k < 2 * C_) ? fc2w[(long)k * C_ + n] : 0.f;
        const float x1 = (k + 1 < 2 * C_) ? fc2w[(long)(k + 1) * C_ + n] : 0.f;
        const __nv_bfloat16 h0 = __float2bfloat16(x0), h1 = __float2bfloat16(x1);
        g_w2[(c * 2 + 0) * 6656 + n * 26 + j] = bf16pair(x0, x1);
        g_w2[(c * 2 + 1) * 6656 + n * 26 + j] =
            bf16pair(x0 - __bfloat162float(h0), x1 - __bfloat162float(h1));
    }
}

// ============================================================================
// K1: KNN. One warp per query, max-replacement top-32 (set-only), REDUX max.
// ============================================================================
__global__ void __launch_bounds__(256) knn_kernel(const float* __restrict__ xyz,
                                                  const float* __restrict__ nxyz) {
    float4* pts = reinterpret_cast<float4*>(dynsm);
    const int b = blockIdx.y;
    const float* xb = xyz + (long)b * N_ * 3;
    for (int j = threadIdx.x; j < N_; j += 256) {
        float x = xb[j * 3 + 0], y = xb[j * 3 + 1], z = xb[j * 3 + 2];
        pts[j] = make_float4(x, y, z, x * x + y * y + z * z);
    }
    __syncthreads();

    const int warp = threadIdx.x >> 5, lane = threadIdx.x & 31;
    const int p = blockIdx.x * 8 + warp;
    const float* q = nxyz + ((long)b * NP_ + p) * 3;
    const float qx = q[0], qy = q[1], qz = q[2];

    float4 c0 = pts[lane];
    unsigned bestU = fmapu(c0.w - 2.f * (qx * c0.x + qy * c0.y + qz * c0.z));
    int besti = lane;
    unsigned curmaxU = __reduce_max_sync(FULL, bestU);

    for (int j0 = K_; j0 < N_; j0 += K_) {
        float4 c = pts[j0 + lane];
        const unsigned dm = fmapu(c.w - 2.f * (qx * c.x + qy * c.y + qz * c.z));
        unsigned mset = __ballot_sync(FULL, dm < curmaxU);
        while (mset) {
            int src = __ffs(mset) - 1;
            mset &= mset - 1;
            const unsigned cdU = __shfl_sync(FULL, dm, src);
            if (cdU < curmaxU) {
                unsigned vict = __ballot_sync(FULL, bestU == curmaxU);
                int vl = __ffs(vict) - 1;
                if (lane == vl) { bestU = cdU; besti = j0 + src; }
                curmaxU = __reduce_max_sync(FULL, bestU);
            }
        }
    }
    g_idx_buf[((long)b * NP_ + p) * K_ + lane] = besti;
}

// ============================================================================
// K2: attn — mma Q GEMM with a 6-pass cp.async-pipelined B stream
// (pass = chunk x part; ping-pong on the two Bbf part-buffers). Pass 0 is
// prefetched at kernel entry and hides under gather+LN.
// ============================================================================
struct __align__(16) SmemAll {
    unsigned Abf[2][128][AP];
    unsigned Bbf[2][256][AP];   // ping-pong buffers X0/X1 (one part each)
    float xsT[CG][XP];
    float pad0[2];
    float qm[G_][C_];
    float gmax[G_][132];
    float z[G_][H_][132];
    float y[G_][H_][132];
    float attnw[G_][H_][K_];
    float sat[G_][C_];
    float pp[2][G_][C_];
    float dd[2][G_][C_];
    int   nidx[G_][K_];
    float q3[G_][4];
};

__global__ void __launch_bounds__(T_, 1) attn_kernel(
    const float* __restrict__ xyz, const float* __restrict__ nxyz,
    const float* __restrict__ featin, const float* __restrict__ wqkv,
    const float* __restrict__ projw, const float* __restrict__ projb,
    const float* __restrict__ densew, const float* __restrict__ denseb,
    const float* __restrict__ n1g, const float* __restrict__ n1b) {
    SmemAll& s = *reinterpret_cast<SmemAll*>(dynsm);
    const int t = threadIdx.x;
    const int w = t >> 5, lane = t & 31;
    const int grp0 = blockIdx.x * G_;
    const int b = grp0 >> 10, p0 = grp0 & 1023;
    const unsigned xaddr[2] = {smem_u32(&s.Bbf[0][0][0]), smem_u32(&s.Bbf[1][0][0])};

    // prefetch B pass 0 (chunk0-hi) — hides under gather + LN
    {
        const uint4* src = reinterpret_cast<const uint4*>(g_wq);
        for (int i = t; i < 1664; i += T_) cp16(xaddr[0] + i * 16, src + i);
        CP_COMMIT();
    }

    if (t < G_ * K_) {
        int g = t >> 5, r = t & 31;
        s.nidx[g][r] = g_idx_buf[(long)(grp0 + g) * K_ + r];
    }
    if (t < G_ * 3) {
        int g = t / 3, c = t % 3;
        s.q3[g][c] = nxyz[((long)b * NP_ + p0 + g) * 3 + c];
    }
    __syncthreads();

    if (t < G_ * K_) {
        int g = t >> 5, r = t & 31;
        int j = s.nidx[g][r];
        const float* xp = xyz + ((long)b * N_ + j) * 3;
        s.xsT[0][g * GP + r] = xp[0] - s.q3[g][0];
        s.xsT[1][g * GP + r] = xp[1] - s.q3[g][1];
        s.xsT[2][g * GP + r] = xp[2] - s.q3[g][2];
    }
    for (int e = t; e < G_ * K_ * CIN; e += T_) {
        int g = e >> 12, r = (e >> 7) & 31, i = e & 127;
        s.xsT[3 + i][g * GP + r] = featin[((long)b * N_ + s.nidx[g][r]) * CIN + i];
    }
    __syncthreads();

    for (int e = t; e < G_ * CG; e += T_) {
        int g = e / CG, i = e - g * CG;
        float m = s.xsT[i][g * GP];
#pragma unroll
        for (int r = 1; r < K_; ++r) m = fmaxf(m, s.xsT[i][g * GP + r]);
        s.gmax[g][i] = m;
    }
    __syncthreads();

    for (int k = 0; k < 8; ++k) {
        const int row = w + 16 * k;
        const int g = row >> 5, r = row & 31;
        float v[5];
        int kn = 0;
        float sum = 0.f;
        for (int ii = lane; ii < CG; ii += 32) { v[kn] = s.xsT[ii][g * GP + r]; sum += v[kn]; ++kn; }
#pragma unroll
        for (int o = 16; o; o >>= 1) sum += __shfl_xor_sync(FULL, sum, o);
        const float m = sum * (1.f / CG);
        float qv = 0.f;
        for (int kk = 0; kk < kn; ++kk) { float d = v[kk] - m; qv += d * d; }
#pragma unroll
        for (int o = 16; o; o >>= 1) qv += __shfl_xor_sync(FULL, qv, o);
        const float rs = rsqrtf(qv * (1.f / CG) + 1e-3f);
        kn = 0;
        for (int ii = lane; ii < CG; ii += 32) {
            s.xsT[ii][g * GP + r] = (v[kn] - m) * rs * n1g[ii] + n1b[ii];
            ++kn;
        }
    }
    __syncthreads();

    // convert A chunk 0 (all 512 threads: 128 rows x 24 words)
    {
        const int mq = t & 127, qd = t >> 7;
        const int colx = (mq >> 5) * GP + (mq & 31);
#pragma unroll
        for (int jj = 0; jj < 6; ++jj) {
            const int j = qd * 6 + jj;
            const int k = 2 * j;
            const float x0 = s.xsT[k][colx];
            const float x1 = s.xsT[k + 1][colx];
            const __nv_bfloat16 h0 = __float2bfloat16(x0), h1 = __float2bfloat16(x1);
            s.Abf[0][mq][j] = (unsigned)__bfloat16_as_ushort(h0) |
                              ((unsigned)__bfloat16_as_ushort(h1) << 16);
            s.Abf[1][mq][j] = bf16pair(x0 - __bfloat162float(h0), x1 - __bfloat162float(h1));
        }
    }
    // prefetch B pass 1 (chunk0-lo)
    {
        const uint4* src = reinterpret_cast<const uint4*>(g_wq + 6656);
        for (int i = t; i < 1664; i += T_) cp16(xaddr[1] + i * 16, src + i);
        CP_COMMIT();
    }

    const int gq = w & 3;
    const int mbase = 32 * gq;
    const int nbase = (w >> 2) * 64;
    const int lp = lane >> 2, lq = lane & 3;
    float cfr[2][8][4];
#pragma unroll
    for (int mt = 0; mt < 2; ++mt)
#pragma unroll
        for (int j = 0; j < 8; ++j)
#pragma unroll
            for (int e = 0; e < 4; ++e) cfr[mt][j][e] = 0.f;

    const unsigned* A0 = &s.Abf[0][0][0];
    const unsigned* A1 = &s.Abf[1][0][0];

    for (int p = 0; p < 6; ++p) {
        if (p >= 1 && p + 1 < 6) {          // prefetch pass p+1 (pass1 issued above)
            const uint4* src = reinterpret_cast<const uint4*>(g_wq + (long)(p + 1) * 6656);
            const unsigned dsta = xaddr[(p + 1) & 1];
            for (int i = t; i < 1664; i += T_) cp16(dsta + i * 16, src + i);
            CP_COMMIT();
        }
        if (p < 5) CP_WAIT1(); else CP_WAIT0();
        __syncthreads();
        const unsigned* BB = &s.Bbf[p & 1][0][0];

        if ((p & 1) == 0) {                 // hi part: hh + lh
#pragma unroll
            for (int ks = 0; ks < 3; ++ks) {
                const int ko = ks * 8 + lq;
                unsigned ah[2][4], al[2][4];
#pragma unroll
                for (int mt = 0; mt < 2; ++mt) {
                    const int r0 = (mbase + mt * 16 + lp) * AP;
                    const int r8 = r0 + 8 * AP;
                    ah[mt][0] = A0[r0 + ko];     ah[mt][1] = A0[r8 + ko];
                    ah[mt][2] = A0[r0 + ko + 4]; ah[mt][3] = A0[r8 + ko + 4];
                    al[mt][0] = A1[r0 + ko];     al[mt][1] = A1[r8 + ko];
                    al[mt][2] = A1[r0 + ko + 4]; al[mt][3] = A1[r8 + ko + 4];
                }
#pragma unroll
                for (int j = 0; j < 8; ++j) {
                    const int nr = (nbase + j * 8 + lp) * AP;
                    const unsigned b0 = BB[nr + ko], b1 = BB[nr + ko + 4];
#pragma unroll
                    for (int mt = 0; mt < 2; ++mt) {
                        mma16816(cfr[mt][j], ah[mt], b0, b1);
                        mma16816(cfr[mt][j], al[mt], b0, b1);
                    }
                }
            }
        } else {                            // lo part: hl
#pragma unroll
            for (int ks = 0; ks < 3; ++ks) {
                const int ko = ks * 8 + lq;
                unsigned ah[2][4];
#pragma unroll
                for (int mt = 0; mt < 2; ++mt) {
                    const int r0 = (mbase + mt * 16 + lp) * AP;
                    const int r8 = r0 + 8 * AP;
                    ah[mt][0] = A0[r0 + ko];     ah[mt][1] = A0[r8 + ko];
                    ah[mt][2] = A0[r0 + ko + 4]; ah[mt][3] = A0[r8 + ko + 4];
                }
#pragma unroll
                for (int j = 0; j < 8; ++j) {
                    const int nr = (nbase + j * 8 + lp) * AP;
                    const unsigned b0 = BB[nr + ko], b1 = BB[nr + ko + 4];
#pragma unroll
                    for (int mt = 0; mt < 2; ++mt)
                        mma16816(cfr[mt][j], ah[mt], b0, b1);
                }
            }
        }
        __syncthreads();

        if ((p & 1) && p < 5) {             // convert A for chunk p/2+1
            const int c = (p >> 1) + 1;
            const int mq = t & 127, qd = t >> 7;
            const int colx = (mq >> 5) * GP + (mq & 31);
#pragma unroll
            for (int jj = 0; jj < 6; ++jj) {
                const int j = qd * 6 + jj;
                const int k = c * KC + 2 * j;
                const float x0 = (k < CG) ? s.xsT[k][colx] : 0.f;
                const float x1 = (k + 1 < CG) ? s.xsT[k + 1][colx] : 0.f;
                const __nv_bfloat16 h0 = __float2bfloat16(x0), h1 = __float2bfloat16(x1);
                s.Abf[0][mq][j] = (unsigned)__bfloat16_as_ushort(h0) |
                                  ((unsigned)__bfloat16_as_ushort(h1) << 16);
                s.Abf[1][mq][j] = bf16pair(x0 - __bfloat162float(h0), x1 - __bfloat162float(h1));
            }
            // visibility: next loop iteration's __syncthreads covers this
        }
    }

#pragma unroll
    for (int j = 0; j < 8; ++j) {
        float ve = fmaxf(fmaxf(cfr[0][j][0], cfr[0][j][2]), fmaxf(cfr[1][j][0], cfr[1][j][2]));
        float vo = fmaxf(fmaxf(cfr[0][j][1], cfr[0][j][3]), fmaxf(cfr[1][j][1], cfr[1][j][3]));
#pragma unroll
        for (int o = 4; o <= 16; o <<= 1) {
            ve = fmaxf(ve, __shfl_xor_sync(FULL, ve, o));
            vo = fmaxf(vo, __shfl_xor_sync(FULL, vo, o));
        }
        if (lane < 4) {
            s.qm[gq][nbase + j * 8 + 2 * lane]     = ve;
            s.qm[gq][nbase + j * 8 + 2 * lane + 1] = vo;
        }
    }
    __syncthreads();

    {
        float4 qa[G_], qb[G_];
#pragma unroll
        for (int g = 0; g < G_; ++g) {
            qa[g] = reinterpret_cast<const float4*>(s.qm[g])[lane];
            qb[g] = reinterpret_cast<const float4*>(s.qm[g])[32 + lane];
        }
        for (int i = w; i < CG; i += 16) {
            const float4* wr = reinterpret_cast<const float4*>(wqkv + (long)i * TC + C_);
            const float4 w0 = wr[lane];
            const float4 w1 = wr[32 + lane];
            float s0[G_], s1[G_];
#pragma unroll
            for (int g = 0; g < G_; ++g) {
                s0[g] = w0.x * qa[g].x + w0.y * qa[g].y + w0.z * qa[g].z + w0.w * qa[g].w;
                s1[g] = w1.x * qb[g].x + w1.y * qb[g].y + w1.z * qb[g].z + w1.w * qb[g].w;
            }
#pragma unroll
            for (int o = 8; o; o >>= 1) {
#pragma unroll
                for (int g = 0; g < G_; ++g) {
                    s0[g] += __shfl_xor_sync(FULL, s0[g], o);
                    s1[g] += __shfl_xor_sync(FULL, s1[g], o);
                }
            }
            if ((lane & 15) == 0) {
                const int h0 = lane >> 4;
#pragma unroll
                for (int g = 0; g < G_; ++g) {
                    s.z[g][h0][i]     = s0[g];
                    s.z[g][h0 + 2][i] = s1[g];
                }
            }
        }
    }
    __syncthreads();

    {
        const int g = w >> 2, h = w & 3, r = lane;
        float a = 0.f;
#pragma unroll 4
        for (int i = 0; i < CG; ++i) a += s.xsT[i][g * GP + r] * s.z[g][h][i];
        a *= 0.0625f;
        float mx = a;
#pragma unroll
        for (int o = 16; o; o >>= 1) mx = fmaxf(mx, __shfl_xor_sync(FULL, mx, o));
        const float e = expf(a - mx);
        float ss = e;
#pragma unroll
        for (int o = 16; o; o >>= 1) ss += __shfl_xor_sync(FULL, ss, o);
        s.attnw[g][h][r] = e / ss;
    }
    __syncthreads();

    for (int e = t; e < G_ * H_ * CG; e += T_) {
        const int i = e % CG;
        const int gh = e / CG;
        const int g = gh >> 2, h = gh & 3;
        const ull* aw = reinterpret_cast<const ull*>(s.attnw[g][h]);
        const ull* xr = reinterpret_cast<const ull*>(&s.xsT[i][g * GP]);
        ull acc = 0ull;
#pragma unroll
        for (int rp = 0; rp < 16; ++rp) fma2(acc, xr[rp], aw[rp]);
        float a, b2; upk2(acc, a, b2);
        s.y[g][h][i] = a + b2;
    }
    __syncthreads();

    // ---- sat partials: thread = (c, K-half); all 4 groups per thread
    {
        const int c = t & 255, half = t >> 8;
        const int h = c >> 6;
        const int i0 = half ? 66 : 0, i1 = half ? CG : 66;
        const float* wv = wqkv + 2 * C_ + c;
        float a0 = 0.f, a1 = 0.f, a2 = 0.f, a3 = 0.f;
#pragma unroll 8
        for (int i = i0; i < i1; ++i) {
            const float wvi = wv[(long)i * TC];
            a0 += s.y[0][h][i] * wvi;
            a1 += s.y[1][h][i] * wvi;
            a2 += s.y[2][h][i] * wvi;
            a3 += s.y[3][h][i] * wvi;
        }
        s.pp[half][0][c] = a0;
        s.pp[half][1][c] = a1;
        s.pp[half][2][c] = a2;
        s.pp[half][3][c] = a3;
    }
    __syncthreads();
    for (int e = t; e < G_ * C_; e += T_) {
        const int g = e >> 8, c = e & 255;
        s.sat[g][c] = s.pp[0][g][c] + s.pp[1][g][c];
    }
    __syncthreads();

    // ---- proj + dense partials: thread = (c, K-half); all 4 groups
    {
        const int c = t & 255, half = t >> 8;
        float p0 = 0.f, p1 = 0.f, p2 = 0.f, p3 = 0.f;
        const int pi0 = half * 128, pi1 = pi0 + 128;
        const float* wp = projw + c;
#pragma unroll 8
        for (int i = pi0; i < pi1; ++i) {
            const float wv = wp[(long)i * C_];
            p0 += s.sat[0][i] * wv;
            p1 += s.sat[1][i] * wv;
            p2 += s.sat[2][i] * wv;
            p3 += s.sat[3][i] * wv;
        }
        float d0 = 0.f, d1 = 0.f, d2 = 0.f, d3 = 0.f;
        const int di0 = half ? 66 : 0, di1 = half ? CG : 66;
        const float* wd = densew + c;
#pragma unroll 8
        for (int i = di0; i < di1; ++i) {
            const float wv = wd[(long)i * C_];
            d0 += s.gmax[0][i] * wv;
            d1 += s.gmax[1][i] * wv;
            d2 += s.gmax[2][i] * wv;
            d3 += s.gmax[3][i] * wv;
        }
        s.pp[half][0][c] = p0; s.pp[half][1][c] = p1;
        s.pp[half][2][c] = p2; s.pp[half][3][c] = p3;
        s.dd[half][0][c] = d0; s.dd[half][1][c] = d1;
        s.dd[half][2][c] = d2; s.dd[half][3][c] = d3;
    }
    __syncthreads();
    for (int e = t; e < G_ * C_; e += T_) {
        const int g = e >> 8, c = e & 255;
        const float pv = s.pp[0][g][c] + s.pp[1][g][c] + projb[c];
        const float dv = s.dd[0][g][c] + s.dd[1][g][c] + denseb[c];
        g_feat_buf[(long)(grp0 + g) * C_ + c] = fmaxf(pv, 0.f) + fmaxf(dv, 0.f);
    }
}

// ============================================================================
// K3: MLP on tensor cores, cp.async double-buffered weight pipeline.
// (round-13 version, unchanged — 184 us measured)
// ============================================================================
constexpr int OFF_X0  = 0;
constexpr int OFF_X1  = 13312;
constexpr int OFF_LN  = 26624;
constexpr int OFF_H   = OFF_LN + 2 * 32 * P1;
constexpr int MLP_WORDS = OFF_H + 2 * 32 * P2;

__global__ void __launch_bounds__(MT_, 1) mlp_kernel(
    const float* __restrict__ fc1b, const float* __restrict__ fc2b,
    const float* __restrict__ n2g, const float* __restrict__ n2b,
    float* __restrict__ out) {
    unsigned* sm = reinterpret_cast<unsigned*>(dynsm);
    unsigned* X[2] = {sm + OFF_X0, sm + OFF_X1};
    unsigned* LN0 = sm + OFF_LN;
    unsigned* LN1 = LN0 + 32 * P1;
    unsigned* H0  = sm + OFF_H;
    unsigned* H1  = H0 + 32 * P2;
    const unsigned xaddr[2] = {smem_u32(X[0]), smem_u32(X[1])};
    const int t = threadIdx.x;
    const int w = t >> 5, lane = t & 31;
    const int lp = lane >> 2, lq = lane & 3;
    const long row0 = (long)blockIdx.x * MR;

    {
        const uint4* src = reinterpret_cast<const uint4*>(g_w1);
        for (int i = t; i < 3328; i += MT_) cp16(xaddr[0] + i * 16, src + i);
        CP_COMMIT();
    }

    for (int i = t; i < 1024; i += MT_) {
        const int part = i >> 9, rr = (i >> 4) & 31, wd = i & 15;
        (part ? LN1 : LN0)[rr * P1 + 128 + wd] = 0u;
    }
    {
        const int part = t >> 8, rr = (t >> 3) & 31, wd = t & 7;
        (part ? H1 : H0)[rr * P2 + 256 + wd] = 0u;
    }

    for (int rr = 0; rr < 2; ++rr) {
        const int r = w + 16 * rr;
        const float2* frow = reinterpret_cast<const float2*>(g_feat_buf + (row0 + r) * C_);
        float2 v[4];
        float sum = 0.f;
#pragma unroll
        for (int k = 0; k < 4; ++k) { v[k] = frow[lane + 32 * k]; sum += v[k].x + v[k].y; }
#pragma unroll
        for (int o = 16; o; o >>= 1) sum += __shfl_xor_sync(FULL, sum, o);
        const float m = sum * (1.f / C_);
        float qv = 0.f;
#pragma unroll
        for (int k = 0; k < 4; ++k) {
            const float dx = v[k].x - m, dy = v[k].y - m;
            qv += dx * dx + dy * dy;
        }
#pragma unroll
        for (int o = 16; o; o >>= 1) qv += __shfl_xor_sync(FULL, qv, o);
        const float rs = rsqrtf(qv * (1.f / C_) + 1e-3f);
#pragma unroll
        for (int k = 0; k < 4; ++k) {
            const int wi = lane + 32 * k;
            const float2 gg = reinterpret_cast<const float2*>(n2g)[wi];
            const float2 bb = reinterpret_cast<const float2*>(n2b)[wi];
            const float x0 = (v[k].x - m) * rs * gg.x + bb.x;
            const float x1 = (v[k].y - m) * rs * gg.y + bb.y;
            const __nv_bfloat16 h0 = __float2bfloat16(x0), h1 = __float2bfloat16(x1);
            LN0[r * P1 + wi] = (unsigned)__bfloat16_as_ushort(h0) |
                               ((unsigned)__bfloat16_as_ushort(h1) << 16);
            LN1[r * P1 + wi] = bf16pair(x0 - __bfloat162float(h0), x1 - __bfloat162float(h1));
        }
    }
    __syncthreads();

    float cfr[2][4][4];
#pragma unroll
    for (int mt = 0; mt < 2; ++mt)
#pragma unroll
        for (int j = 0; j < 4; ++j)
#pragma unroll
            for (int e = 0; e < 4; ++e) cfr[mt][j][e] = 0.f;

    for (int p = 0; p < 12; ++p) {
        {
            const uint4* src = (p + 1 < 12)
                ? reinterpret_cast<const uint4*>(g_w1 + (long)(p + 1) * 13312)
                : reinterpret_cast<const uint4*>(g_w2);
            const unsigned dsta = xaddr[(p + 1) & 1];
            for (int i = t; i < 3328; i += MT_) cp16(dsta + i * 16, src + i);
            CP_COMMIT();
        }
        CP_WAIT1();
        __syncthreads();
        const unsigned* BBF = X[p & 1];
        const int c = p >> 1;
        if ((p & 1) == 0) {
#pragma unroll
            for (int ks = 0; ks < 3; ++ks) {
                const int ko = c * 24 + ks * 8 + lq;
                const int kb = ks * 8 + lq;
                unsigned ah[2][4], al[2][4];
#pragma unroll
                for (int mt = 0; mt < 2; ++mt) {
                    const int r0 = (mt * 16 + lp) * P1;
                    ah[mt][0] = LN0[r0 + ko];     ah[mt][1] = LN0[r0 + 8 * P1 + ko];
                    ah[mt][2] = LN0[r0 + ko + 4]; ah[mt][3] = LN0[r0 + 8 * P1 + ko + 4];
                    al[mt][0] = LN1[r0 + ko];     al[mt][1] = LN1[r0 + 8 * P1 + ko];
                    al[mt][2] = LN1[r0 + ko + 4]; al[mt][3] = LN1[r0 + 8 * P1 + ko + 4];
                }
#pragma unroll
                for (int j = 0; j < 4; ++j) {
                    const int nr = (w * 32 + j * 8 + lp) * AP;
                    const unsigned b0 = BBF[nr + kb], b1 = BBF[nr + kb + 4];
#pragma unroll
                    for (int mt = 0; mt < 2; ++mt) {
                        mma16816(cfr[mt][j], ah[mt], b0, b1);
                        mma16816(cfr[mt][j], al[mt], b0, b1);
                    }
                }
            }
        } else {
#pragma unroll
            for (int ks = 0; ks < 3; ++ks) {
                const int ko = c * 24 + ks * 8 + lq;
                const int kb = ks * 8 + lq;
                unsigned ah[2][4];
#pragma unroll
                for (int mt = 0; mt < 2; ++mt) {
                    const int r0 = (mt * 16 + lp) * P1;
                    ah[mt][0] = LN0[r0 + ko];     ah[mt][1] = LN0[r0 + 8 * P1 + ko];
                    ah[mt][2] = LN0[r0 + ko + 4]; ah[mt][3] = LN0[r0 + 8 * P1 + ko + 4];
                }
#pragma unroll
                for (int j = 0; j < 4; ++j) {
                    const int nr = (w * 32 + j * 8 + lp) * AP;
                    const unsigned b0 = BBF[nr + kb], b1 = BBF[nr + kb + 4];
#pragma unroll
                    for (int mt = 0; mt < 2; ++mt)
                        mma16816(cfr[mt][j], ah[mt], b0, b1);
                }
            }
        }
        __syncthreads();
    }

#pragma unroll
    for (int mt = 0; mt < 2; ++mt)
#pragma unroll
    for (int j = 0; j < 4; ++j) {
        const float2 bj = *reinterpret_cast<const float2*>(fc1b + w * 32 + j * 8 + 2 * lq);
        const int wd = w * 16 + j * 4 + lq;
        {
            const int row = mt * 16 + lp;
            const float v0 = fmaxf(cfr[mt][j][0] + bj.x, 0.f);
            const float v1 = fmaxf(cfr[mt][j][1] + bj.y, 0.f);
            const __nv_bfloat16 h0 = __float2bfloat16(v0), h1 = __float2bfloat16(v1);
            H0[row * P2 + wd] = (unsigned)__bfloat16_as_ushort(h0) |
                                ((unsigned)__bfloat16_as_ushort(h1) << 16);
            H1[row * P2 + wd] = bf16pair(v0 - __bfloat162float(h0), v1 - __bfloat162float(h1));
        }
        {
            const int row = mt * 16 + lp + 8;
            const float v0 = fmaxf(cfr[mt][j][2] + bj.x, 0.f);
            const float v1 = fmaxf(cfr[mt][j][3] + bj.y, 0.f);
            const __nv_bfloat16 h0 = __float2bfloat16(v0), h1 = __float2bfloat16(v1);
            H0[row * P2 + wd] = (unsigned)__bfloat16_as_ushort(h0) |
                                ((unsigned)__bfloat16_as_ushort(h1) << 16);
            H1[row * P2 + wd] = bf16pair(v0 - __bfloat162float(h0), v1 - __bfloat162float(h1));
        }
    }
    __syncthreads();

    float c2[2][2][4];
#pragma unroll
    for (int mt = 0; mt < 2; ++mt)
#pragma unroll
        for (int j = 0; j < 2; ++j)
#pragma unroll
            for (int e = 0; e < 4; ++e) c2[mt][j][e] = 0.f;

    for (int c = 0; c < 11; ++c) {
        if (c + 1 < 11) {
            const uint4* src = reinterpret_cast<const uint4*>(g_w2 + (long)(c + 1) * 13312);
            const unsigned dsta = xaddr[(c + 1) & 1];
            for (int i = t; i < 3328; i += MT_) cp16(dsta + i * 16, src + i);
            CP_COMMIT();
            CP_WAIT1();
        } else {
            CP_WAIT0();
        }
        __syncthreads();
        const unsigned* BBF = X[c & 1];
#pragma unroll
        for (int ks = 0; ks < 3; ++ks) {
            const int ko = c * 24 + ks * 8 + lq;
            const int kb = ks * 8 + lq;
            unsigned ah[2][4], al[2][4];
#pragma unroll
            for (int mt = 0; mt < 2; ++mt) {
                const int r0 = (mt * 16 + lp) * P2;
                ah[mt][0] = H0[r0 + ko];     ah[mt][1] = H0[r0 + 8 * P2 + ko];
                ah[mt][2] = H0[r0 + ko + 4]; ah[mt][3] = H0[r0 + 8 * P2 + ko + 4];
                al[mt][0] = H1[r0 + ko];     al[mt][1] = H1[r0 + 8 * P2 + ko];
                al[mt][2] = H1[r0 + ko + 4]; al[mt][3] = H1[r0 + 8 * P2 + ko + 4];
            }
#pragma unroll
            for (int j = 0; j < 2; ++j) {
                const int nr = (w * 16 + j * 8 + lp) * AP;
                const unsigned bh0 = BBF[nr + kb], bh1 = BBF[nr + kb + 4];
                const unsigned bl0 = BBF[6656 + nr + kb], bl1 = BBF[6656 + nr + kb + 4];
#pragma unroll
                for (int mt = 0; mt < 2; ++mt) {
                    mma16816(c2[mt][j], ah[mt], bh0, bh1);
                    mma16816(c2[mt][j], al[mt], bh0, bh1);
                    mma16816(c2[mt][j], ah[mt], bl0, bl1);
                }
            }
        }
        __syncthreads();
    }

#pragma unroll
    for (int mt = 0; mt < 2; ++mt)
#pragma unroll
    for (int j = 0; j < 2; ++j) {
        const int col = w * 16 + j * 8 + 2 * lq;
        const float2 bj = *reinterpret_cast<const float2*>(fc2b + col);
        {
            const long row = row0 + mt * 16 + lp;
            const float2 res = *reinterpret_cast<const float2*>(g_feat_buf + row * C_ + col);
            float2 o;
            o.x = c2[mt][j][0] + bj.x + res.x;
            o.y = c2[mt][j][1] + bj.y + res.y;
            *reinterpret_cast<float2*>(out + row * C_ + col) = o;
        }
        {
            const long row = row0 + mt * 16 + lp + 8;
            const float2 res = *reinterpret_cast<const float2*>(g_feat_buf + row * C_ + col);
            float2 o;
            o.x = c2[mt][j][2] + bj.x + res.x;
            o.y = c2[mt][j][3] + bj.y + res.y;
            *reinterpret_cast<float2*>(out + row * C_ + col) = o;
        }
    }
}

// ============================================================================
extern "C" void kernel_launch(void* const* d_in, const int* in_sizes, int n_in,
                              void* d_out, int out_size) {
    const float* xyz    = (const float*)d_in[0];
    const float* nxyz   = (const float*)d_in[1];
    const float* featin = (const float*)d_in[2];
    const float* wqkv   = (const float*)d_in[3];
    const float* projw  = (const float*)d_in[4];
    const float* projb  = (const float*)d_in[5];
    const float* densew = (const float*)d_in[6];
    const float* denseb = (const float*)d_in[7];
    const float* fc1w   = (const float*)d_in[8];
    const float* fc1b   = (const float*)d_in[9];
    const float* fc2w   = (const float*)d_in[10];
    const float* fc2b   = (const float*)d_in[11];
    const float* n1g    = (const float*)d_in[12];
    const float* n1b    = (const float*)d_in[13];
    const float* n2g    = (const float*)d_in[14];
    const float* n2b    = (const float*)d_in[15];
    float* out = (float*)d_out;

    (void)in_sizes; (void)n_in; (void)out_size;

    const int knn_smem  = N_ * (int)sizeof(float4);            // 64 KB
    const int attn_smem = (int)sizeof(SmemAll);                // ~194 KB
    const int mlp_smem  = MLP_WORDS * 4;                       // ~218 KB
    cudaFuncSetAttribute(knn_kernel, cudaFuncAttributeMaxDynamicSharedMemorySize, knn_smem);
    cudaFuncSetAttribute(attn_kernel, cudaFuncAttributeMaxDynamicSharedMemorySize, attn_smem);
    cudaFuncSetAttribute(mlp_kernel, cudaFuncAttributeMaxDynamicSharedMemorySize, mlp_smem);

    prep_kernel<<<312, 512>>>(wqkv, fc1w, fc2w);
    knn_kernel<<<dim3(NP_ / 8, B_), 256, knn_smem>>>(xyz, nxyz);
    attn_kernel<<<B_ * NP_ / G_, T_, attn_smem>>>(xyz, nxyz, featin, wqkv, projw, projb,
                                                  densew, denseb, n1g, n1b);
    mlp_kernel<<<B_ * NP_ / MR, MT_, mlp_smem>>>(fc1b, fc2b, n2g, n2b, out);
}

// round 15
// speedup vs baseline: 1.1090x; 1.1090x over previous
#include <cuda_runtime.h>
#include <cuda_bf16.h>
#include <cstdint>

typedef unsigned long long ull;
#define FULL 0xffffffffu

constexpr int B_  = 16;
constexpr int N_  = 4096;
constexpr int NP_ = 1024;
constexpr int K_  = 32;
constexpr int CIN = 128;
constexpr int CG  = 131;   // 3 + 128
constexpr int C_  = 256;
constexpr int H_  = 4;
constexpr int D_  = 64;
constexpr int TC  = 768;   // 3*C
constexpr int G_  = 4;     // groups per attn block (M = 128 rows)
constexpr int GP  = 34;    // per-group sub-pitch (floats) in xsT row
constexpr int XP  = 138;   // xsT row pitch (floats)
constexpr int T_  = 512;   // attn threads
constexpr int KC  = 48;    // K-chunk for mma (AP=26 conflict-free pattern)
constexpr int AP  = 26;    // A/B smem row pitch in 32-bit words
constexpr int MR  = 32;    // mlp rows per block (2 m-tiles)
constexpr int MT_ = 512;   // mlp threads
constexpr int P1  = 154;   // lnPk pitch words (154 mod 32 == 26)
constexpr int P2  = 282;   // hPk pitch words  (282 mod 32 == 26)

// scratch (device globals: allocation-free rule; zero-initialized)
__device__ int   g_idx_buf[B_ * NP_ * K_];
__device__ float g_feat_buf[B_ * NP_ * C_];
// weights as bf16 hi/lo, PRE-PITCHED [chunk][part][n][26 words] (words 24,25 = 0)
__device__ __align__(16) unsigned g_wq[3 * 2 * 256 * 26];
__device__ __align__(16) unsigned g_w1[6 * 2 * 512 * 26];
__device__ __align__(16) unsigned g_w2[11 * 2 * 256 * 26];

extern __shared__ __align__(16) unsigned char dynsm[];

// ---------------- packed f32x2 helpers
__device__ __forceinline__ ull pk2(float a, float b) {
    ull r;
    asm("mov.b64 %0, {%1,%2};" : "=l"(r) : "f"(a), "f"(b));
    return r;
}
__device__ __forceinline__ void upk2(ull v, float& a, float& b) {
    asm("mov.b64 {%0,%1}, %2;" : "=f"(a), "=f"(b) : "l"(v));
}
__device__ __forceinline__ void fma2(ull& d, ull a, ull b) {
    asm("fma.rn.f32x2 %0, %1, %2, %3;" : "=l"(d) : "l"(a), "l"(b), "l"(d));
}

// ---------------- warp mma m16n8k16 bf16 (base PTX, works at compute_103)
__device__ __forceinline__ void mma16816(float* d, const unsigned* a, unsigned b0, unsigned b1) {
    asm volatile(
        "mma.sync.aligned.m16n8k16.row.col.f32.bf16.bf16.f32 "
        "{%0,%1,%2,%3}, {%4,%5,%6,%7}, {%8,%9}, {%0,%1,%2,%3};"
        : "+f"(d[0]), "+f"(d[1]), "+f"(d[2]), "+f"(d[3])
        : "r"(a[0]), "r"(a[1]), "r"(a[2]), "r"(a[3]), "r"(b0), "r"(b1));
}
__device__ __forceinline__ unsigned bf16pair(float x0, float x1) {
    const __nv_bfloat16 h0 = __float2bfloat16(x0), h1 = __float2bfloat16(x1);
    return (unsigned)__bfloat16_as_ushort(h0) | ((unsigned)__bfloat16_as_ushort(h1) << 16);
}
__device__ __forceinline__ unsigned smem_u32(const void* p) {
    unsigned a;
    asm("{ .reg .u64 t; cvta.to.shared.u64 t, %1; cvt.u32.u64 %0, t; }" : "=r"(a) : "l"(p));
    return a;
}
// ---------------- cp.async helpers (base PTX sm_80+)
__device__ __forceinline__ void cp16(unsigned smaddr, const void* gptr) {
    asm volatile("cp.async.cg.shared.global [%0], [%1], 16;" :: "r"(smaddr), "l"(gptr));
}
#define CP_COMMIT() asm volatile("cp.async.commit_group;" ::: "memory")
#define CP_WAIT1()  asm volatile("cp.async.wait_group 1;" ::: "memory")
#define CP_WAIT0()  asm volatile("cp.async.wait_group 0;" ::: "memory")

// monotone float -> uint map (order preserving)
__device__ __forceinline__ unsigned fmapu(float f) {
    unsigned u = __float_as_uint(f);
    return (u & 0x80000000u) ? ~u : (u | 0x80000000u);
}

// ============================================================================
// K0: prep — convert Wq, fc1w, fc2w to bf16 hi/lo pre-pitched layouts.
// ============================================================================
__global__ void __launch_bounds__(512) prep_kernel(const float* __restrict__ wqkv,
                                                   const float* __restrict__ fc1w,
                                                   const float* __restrict__ fc2w) {
    const int idx = blockIdx.x * 512 + threadIdx.x;
    if (idx < 18432) {                       // Wq: 3 chunks x 256 n x 24 j
        const int c = idx / 6144, rem = idx % 6144;
        const int n = rem / 24, j = rem % 24;
        const int k = c * KC + 2 * j;
        const float x0 = (k < CG) ? wqkv[(long)k * TC + n] : 0.f;
        const float x1 = (k + 1 < CG) ? wqkv[(long)(k + 1) * TC + n] : 0.f;
        const __nv_bfloat16 h0 = __float2bfloat16(x0), h1 = __float2bfloat16(x1);
        g_wq[(c * 2 + 0) * 6656 + n * 26 + j] = bf16pair(x0, x1);
        g_wq[(c * 2 + 1) * 6656 + n * 26 + j] =
            bf16pair(x0 - __bfloat162float(h0), x1 - __bfloat162float(h1));
    } else if (idx < 92160) {                // fc1w: 6 chunks x 512 n x 24 j
        const int i = idx - 18432;
        const int c = i / 12288, rem = i % 12288;
        const int n = rem / 24, j = rem % 24;
        const int k = c * KC + 2 * j;
        const float x0 = (k < C_) ? fc1w[(long)k * (2 * C_) + n] : 0.f;
        const float x1 = (k + 1 < C_) ? fc1w[(long)(k + 1) * (2 * C_) + n] : 0.f;
        const __nv_bfloat16 h0 = __float2bfloat16(x0), h1 = __float2bfloat16(x1);
        g_w1[(c * 2 + 0) * 13312 + n * 26 + j] = bf16pair(x0, x1);
        g_w1[(c * 2 + 1) * 13312 + n * 26 + j] =
            bf16pair(x0 - __bfloat162float(h0), x1 - __bfloat162float(h1));
    } else if (idx < 159744) {               // fc2w: 11 chunks x 256 n x 24 j
        const int i = idx - 92160;
        const int c = i / 6144, rem = i % 6144;
        const int n = rem / 24, j = rem % 24;
        const int k = c * KC + 2 * j;
        const float x0 = (k < 2 * C_) ? fc2w[(long)k * C_ + n] : 0.f;
        const float x1 = (k + 1 < 2 * C_) ? fc2w[(long)(k + 1) * C_ + n] : 0.f;
        const __nv_bfloat16 h0 = __float2bfloat16(x0), h1 = __float2bfloat16(x1);
        g_w2[(c * 2 + 0) * 6656 + n * 26 + j] = bf16pair(x0, x1);
        g_w2[(c * 2 + 1) * 6656 + n * 26 + j] =
            bf16pair(x0 - __bfloat162float(h0), x1 - __bfloat162float(h1));
    }
}

// ============================================================================
// K1: KNN. One warp per query, max-replacement top-32 (set-only), REDUX max.
// ============================================================================
__global__ void __launch_bounds__(256) knn_kernel(const float* __restrict__ xyz,
                                                  const float* __restrict__ nxyz) {
    float4* pts = reinterpret_cast<float4*>(dynsm);
    const int b = blockIdx.y;
    const float* xb = xyz + (long)b * N_ * 3;
    for (int j = threadIdx.x; j < N_; j += 256) {
        float x = xb[j * 3 + 0], y = xb[j * 3 + 1], z = xb[j * 3 + 2];
        pts[j] = make_float4(x, y, z, x * x + y * y + z * z);
    }
    __syncthreads();

    const int warp = threadIdx.x >> 5, lane = threadIdx.x & 31;
    const int p = blockIdx.x * 8 + warp;
    const float* q = nxyz + ((long)b * NP_ + p) * 3;
    const float qx = q[0], qy = q[1], qz = q[2];

    float4 c0 = pts[lane];
    unsigned bestU = fmapu(c0.w - 2.f * (qx * c0.x + qy * c0.y + qz * c0.z));
    int besti = lane;
    unsigned curmaxU = __reduce_max_sync(FULL, bestU);

    for (int j0 = K_; j0 < N_; j0 += K_) {
        float4 c = pts[j0 + lane];
        const unsigned dm = fmapu(c.w - 2.f * (qx * c.x + qy * c.y + qz * c.z));
        unsigned mset = __ballot_sync(FULL, dm < curmaxU);
        while (mset) {
            int src = __ffs(mset) - 1;
            mset &= mset - 1;
            const unsigned cdU = __shfl_sync(FULL, dm, src);
            if (cdU < curmaxU) {
                unsigned vict = __ballot_sync(FULL, bestU == curmaxU);
                int vl = __ffs(vict) - 1;
                if (lane == vl) { bestU = cdU; besti = j0 + src; }
                curmaxU = __reduce_max_sync(FULL, bestU);
            }
        }
    }
    g_idx_buf[((long)b * NP_ + p) * K_ + lane] = besti;
}

// ============================================================================
// K2: attn — round-13 structure (both B parts resident, 3 chunks, warp-split
// prologue) + chunk-0 B prefetched by cp.async at entry, float4 gather, and
// n1g/n1b cached in smem.
// ============================================================================
struct __align__(16) SmemAll {
    unsigned Abf[2][128][AP];
    unsigned Bbf[2][256][AP];
    float xsT[CG][XP];
    float pad0[2];
    float qm[G_][C_];
    float gmax[G_][132];
    float z[G_][H_][132];
    float y[G_][H_][132];
    float attnw[G_][H_][K_];
    float sat[G_][C_];
    float pp[2][G_][C_];
    float dd[2][G_][C_];
    float n1gS[132];
    float n1bS[132];
    int   nidx[G_][K_];
    float q3[G_][4];
};

__global__ void __launch_bounds__(T_, 1) attn_kernel(
    const float* __restrict__ xyz, const float* __restrict__ nxyz,
    const float* __restrict__ featin, const float* __restrict__ wqkv,
    const float* __restrict__ projw, const float* __restrict__ projb,
    const float* __restrict__ densew, const float* __restrict__ denseb,
    const float* __restrict__ n1g, const float* __restrict__ n1b) {
    SmemAll& s = *reinterpret_cast<SmemAll*>(dynsm);
    const int t = threadIdx.x;
    const int w = t >> 5, lane = t & 31;
    const int grp0 = blockIdx.x * G_;
    const int b = grp0 >> 10, p0 = grp0 & 1023;

    // prefetch chunk-0 B (both parts) — drains under gather + LN
    {
        const unsigned ba = smem_u32(&s.Bbf[0][0][0]);
        const uint4* src = reinterpret_cast<const uint4*>(g_wq);
        for (int i = t; i < 3328; i += T_) cp16(ba + i * 16, src + i);
        CP_COMMIT();
    }

    if (t < G_ * K_) {
        int g = t >> 5, r = t & 31;
        s.nidx[g][r] = g_idx_buf[(long)(grp0 + g) * K_ + r];
    }
    if (t < G_ * 3) {
        int g = t / 3, c = t % 3;
        s.q3[g][c] = nxyz[((long)b * NP_ + p0 + g) * 3 + c];
    }
    if (t >= 128 && t < 128 + CG) {
        s.n1gS[t - 128] = n1g[t - 128];
        s.n1bS[t - 128] = n1b[t - 128];
    }
    __syncthreads();

    if (t < G_ * K_) {
        int g = t >> 5, r = t & 31;
        int j = s.nidx[g][r];
        const float* xp = xyz + ((long)b * N_ + j) * 3;
        s.xsT[0][g * GP + r] = xp[0] - s.q3[g][0];
        s.xsT[1][g * GP + r] = xp[1] - s.q3[g][1];
        s.xsT[2][g * GP + r] = xp[2] - s.q3[g][2];
    }
    // gather features as float4: 4096 vec4 elements
    for (int e = t; e < G_ * K_ * (CIN / 4); e += T_) {
        const int g = e >> 10, r = (e >> 5) & 31, i4 = e & 31;
        const float4 v = *reinterpret_cast<const float4*>(
            featin + ((long)b * N_ + s.nidx[g][r]) * CIN + 4 * i4);
        const int col = g * GP + r;
        s.xsT[3 + 4 * i4 + 0][col] = v.x;
        s.xsT[3 + 4 * i4 + 1][col] = v.y;
        s.xsT[3 + 4 * i4 + 2][col] = v.z;
        s.xsT[3 + 4 * i4 + 3][col] = v.w;
    }
    __syncthreads();

    for (int e = t; e < G_ * CG; e += T_) {
        int g = e / CG, i = e - g * CG;
        float m = s.xsT[i][g * GP];
#pragma unroll
        for (int r = 1; r < K_; ++r) m = fmaxf(m, s.xsT[i][g * GP + r]);
        s.gmax[g][i] = m;
    }
    __syncthreads();

    for (int k = 0; k < 8; ++k) {
        const int row = w + 16 * k;
        const int g = row >> 5, r = row & 31;
        float v[5];
        int kn = 0;
        float sum = 0.f;
        for (int ii = lane; ii < CG; ii += 32) { v[kn] = s.xsT[ii][g * GP + r]; sum += v[kn]; ++kn; }
#pragma unroll
        for (int o = 16; o; o >>= 1) sum += __shfl_xor_sync(FULL, sum, o);
        const float m = sum * (1.f / CG);
        float qv = 0.f;
        for (int kk = 0; kk < kn; ++kk) { float d = v[kk] - m; qv += d * d; }
#pragma unroll
        for (int o = 16; o; o >>= 1) qv += __shfl_xor_sync(FULL, qv, o);
        const float rs = rsqrtf(qv * (1.f / CG) + 1e-3f);
        kn = 0;
        for (int ii = lane; ii < CG; ii += 32) {
            s.xsT[ii][g * GP + r] = (v[kn] - m) * rs * s.n1gS[ii] + s.n1bS[ii];
            ++kn;
        }
    }
    __syncthreads();

    const int gq = w & 3;
    const int mbase = 32 * gq;
    const int nbase = (w >> 2) * 64;
    const int lp = lane >> 2, lq = lane & 3;
    float cfr[2][8][4];
#pragma unroll
    for (int mt = 0; mt < 2; ++mt)
#pragma unroll
        for (int j = 0; j < 8; ++j)
#pragma unroll
            for (int e = 0; e < 4; ++e) cfr[mt][j][e] = 0.f;

    const unsigned* A0 = &s.Abf[0][0][0];
    const unsigned* A1 = &s.Abf[1][0][0];
    const unsigned* B0 = &s.Bbf[0][0][0];
    const unsigned* B1 = &s.Bbf[1][0][0];

    for (int c = 0; c < 3; ++c) {
        if (c == 0) {
            // chunk-0 A convert with all 512 threads (B arrives via cp.async)
            const int mq = t & 127, qd = t >> 7;
            const int colx = (mq >> 5) * GP + (mq & 31);
#pragma unroll
            for (int jj = 0; jj < 6; ++jj) {
                const int j = qd * 6 + jj;
                const int k = 2 * j;
                const float x0 = s.xsT[k][colx];
                const float x1 = s.xsT[k + 1][colx];
                const __nv_bfloat16 h0 = __float2bfloat16(x0), h1 = __float2bfloat16(x1);
                s.Abf[0][mq][j] = (unsigned)__bfloat16_as_ushort(h0) |
                                  ((unsigned)__bfloat16_as_ushort(h1) << 16);
                s.Abf[1][mq][j] = bf16pair(x0 - __bfloat162float(h0), x1 - __bfloat162float(h1));
            }
            CP_WAIT0();
        } else if (t < 256) {
            // warp-split prologue: warps 0-7 convert A
            const int mq = t & 127, qd = t >> 7;
            const int colx = (mq >> 5) * GP + (mq & 31);
#pragma unroll
            for (int jj = 0; jj < 12; ++jj) {
                const int j = qd * 12 + jj;
                const int k = c * KC + 2 * j;
                const float x0 = (k < CG) ? s.xsT[k][colx] : 0.f;
                const float x1 = (k + 1 < CG) ? s.xsT[k + 1][colx] : 0.f;
                const __nv_bfloat16 h0 = __float2bfloat16(x0), h1 = __float2bfloat16(x1);
                s.Abf[0][mq][j] = (unsigned)__bfloat16_as_ushort(h0) |
                                  ((unsigned)__bfloat16_as_ushort(h1) << 16);
                s.Abf[1][mq][j] = bf16pair(x0 - __bfloat162float(h0), x1 - __bfloat162float(h1));
            }
        } else {
            // warps 8-15 stream B (both parts, contiguous, pre-pitched)
            const uint4* src = reinterpret_cast<const uint4*>(g_wq + (long)c * 13312);
            uint4* dst = reinterpret_cast<uint4*>(&s.Bbf[0][0][0]);
#pragma unroll
            for (int i = 0; i < 13; ++i) dst[(t - 256) + 256 * i] = src[(t - 256) + 256 * i];
        }
        __syncthreads();

#pragma unroll
        for (int ks = 0; ks < 3; ++ks) {
            const int ko = ks * 8 + lq;
            unsigned ah[2][4], al[2][4];
#pragma unroll
            for (int mt = 0; mt < 2; ++mt) {
                const int r0 = (mbase + mt * 16 + lp) * AP;
                const int r8 = r0 + 8 * AP;
                ah[mt][0] = A0[r0 + ko];     ah[mt][1] = A0[r8 + ko];
                ah[mt][2] = A0[r0 + ko + 4]; ah[mt][3] = A0[r8 + ko + 4];
                al[mt][0] = A1[r0 + ko];     al[mt][1] = A1[r8 + ko];
                al[mt][2] = A1[r0 + ko + 4]; al[mt][3] = A1[r8 + ko + 4];
            }
#pragma unroll
            for (int j = 0; j < 8; ++j) {
                const int nr = (nbase + j * 8 + lp) * AP;
                const unsigned bh0 = B0[nr + ko], bh1 = B0[nr + ko + 4];
                const unsigned bl0 = B1[nr + ko], bl1 = B1[nr + ko + 4];
#pragma unroll
                for (int mt = 0; mt < 2; ++mt) {
                    mma16816(cfr[mt][j], ah[mt], bh0, bh1);
                    mma16816(cfr[mt][j], ah[mt], bl0, bl1);
                    mma16816(cfr[mt][j], al[mt], bh0, bh1);
                }
            }
        }
        __syncthreads();
    }

#pragma unroll
    for (int j = 0; j < 8; ++j) {
        float ve = fmaxf(fmaxf(cfr[0][j][0], cfr[0][j][2]), fmaxf(cfr[1][j][0], cfr[1][j][2]));
        float vo = fmaxf(fmaxf(cfr[0][j][1], cfr[0][j][3]), fmaxf(cfr[1][j][1], cfr[1][j][3]));
#pragma unroll
        for (int o = 4; o <= 16; o <<= 1) {
            ve = fmaxf(ve, __shfl_xor_sync(FULL, ve, o));
            vo = fmaxf(vo, __shfl_xor_sync(FULL, vo, o));
        }
        if (lane < 4) {
            s.qm[gq][nbase + j * 8 + 2 * lane]     = ve;
            s.qm[gq][nbase + j * 8 + 2 * lane + 1] = vo;
        }
    }
    __syncthreads();

    {
        float4 qa[G_], qb[G_];
#pragma unroll
        for (int g = 0; g < G_; ++g) {
            qa[g] = reinterpret_cast<const float4*>(s.qm[g])[lane];
            qb[g] = reinterpret_cast<const float4*>(s.qm[g])[32 + lane];
        }
        for (int i = w; i < CG; i += 16) {
            const float4* wr = reinterpret_cast<const float4*>(wqkv + (long)i * TC + C_);
            const float4 w0 = wr[lane];
            const float4 w1 = wr[32 + lane];
            float s0[G_], s1[G_];
#pragma unroll
            for (int g = 0; g < G_; ++g) {
                s0[g] = w0.x * qa[g].x + w0.y * qa[g].y + w0.z * qa[g].z + w0.w * qa[g].w;
                s1[g] = w1.x * qb[g].x + w1.y * qb[g].y + w1.z * qb[g].z + w1.w * qb[g].w;
            }
#pragma unroll
            for (int o = 8; o; o >>= 1) {
#pragma unroll
                for (int g = 0; g < G_; ++g) {
                    s0[g] += __shfl_xor_sync(FULL, s0[g], o);
                    s1[g] += __shfl_xor_sync(FULL, s1[g], o);
                }
            }
            if ((lane & 15) == 0) {
                const int h0 = lane >> 4;
#pragma unroll
                for (int g = 0; g < G_; ++g) {
                    s.z[g][h0][i]     = s0[g];
                    s.z[g][h0 + 2][i] = s1[g];
                }
            }
        }
    }
    __syncthreads();

    {
        const int g = w >> 2, h = w & 3, r = lane;
        float a = 0.f;
#pragma unroll 4
        for (int i = 0; i < CG; ++i) a += s.xsT[i][g * GP + r] * s.z[g][h][i];
        a *= 0.0625f;
        float mx = a;
#pragma unroll
        for (int o = 16; o; o >>= 1) mx = fmaxf(mx, __shfl_xor_sync(FULL, mx, o));
        const float e = expf(a - mx);
        float ss = e;
#pragma unroll
        for (int o = 16; o; o >>= 1) ss += __shfl_xor_sync(FULL, ss, o);
        s.attnw[g][h][r] = e / ss;
    }
    __syncthreads();

    for (int e = t; e < G_ * H_ * CG; e += T_) {
        const int i = e % CG;
        const int gh = e / CG;
        const int g = gh >> 2, h = gh & 3;
        const ull* aw = reinterpret_cast<const ull*>(s.attnw[g][h]);
        const ull* xr = reinterpret_cast<const ull*>(&s.xsT[i][g * GP]);
        ull acc = 0ull;
#pragma unroll
        for (int rp = 0; rp < 16; ++rp) fma2(acc, xr[rp], aw[rp]);
        float a, b2; upk2(acc, a, b2);
        s.y[g][h][i] = a + b2;
    }
    __syncthreads();

    // ---- sat partials: thread = (c, K-half); all 4 groups per thread
    {
        const int c = t & 255, half = t >> 8;
        const int h = c >> 6;
        const int i0 = half ? 66 : 0, i1 = half ? CG : 66;
        const float* wv = wqkv + 2 * C_ + c;
        float a0 = 0.f, a1 = 0.f, a2 = 0.f, a3 = 0.f;
#pragma unroll 8
        for (int i = i0; i < i1; ++i) {
            const float wvi = wv[(long)i * TC];
            a0 += s.y[0][h][i] * wvi;
            a1 += s.y[1][h][i] * wvi;
            a2 += s.y[2][h][i] * wvi;
            a3 += s.y[3][h][i] * wvi;
        }
        s.pp[half][0][c] = a0;
        s.pp[half][1][c] = a1;
        s.pp[half][2][c] = a2;
        s.pp[half][3][c] = a3;
    }
    __syncthreads();
    for (int e = t; e < G_ * C_; e += T_) {
        const int g = e >> 8, c = e & 255;
        s.sat[g][c] = s.pp[0][g][c] + s.pp[1][g][c];
    }
    __syncthreads();

    // ---- proj + dense partials: thread = (c, K-half); all 4 groups
    {
        const int c = t & 255, half = t >> 8;
        float p0 = 0.f, p1 = 0.f, p2 = 0.f, p3 = 0.f;
        const int pi0 = half * 128, pi1 = pi0 + 128;
        const float* wp = projw + c;
#pragma unroll 8
        for (int i = pi0; i < pi1; ++i) {
            const float wv = wp[(long)i * C_];
            p0 += s.sat[0][i] * wv;
            p1 += s.sat[1][i] * wv;
            p2 += s.sat[2][i] * wv;
            p3 += s.sat[3][i] * wv;
        }
        float d0 = 0.f, d1 = 0.f, d2 = 0.f, d3 = 0.f;
        const int di0 = half ? 66 : 0, di1 = half ? CG : 66;
        const float* wd = densew + c;
#pragma unroll 8
        for (int i = di0; i < di1; ++i) {
            const float wv = wd[(long)i * C_];
            d0 += s.gmax[0][i] * wv;
            d1 += s.gmax[1][i] * wv;
            d2 += s.gmax[2][i] * wv;
            d3 += s.gmax[3][i] * wv;
        }
        s.pp[half][0][c] = p0; s.pp[half][1][c] = p1;
        s.pp[half][2][c] = p2; s.pp[half][3][c] = p3;
        s.dd[half][0][c] = d0; s.dd[half][1][c] = d1;
        s.dd[half][2][c] = d2; s.dd[half][3][c] = d3;
    }
    __syncthreads();
    for (int e = t; e < G_ * C_; e += T_) {
        const int g = e >> 8, c = e & 255;
        const float pv = s.pp[0][g][c] + s.pp[1][g][c] + projb[c];
        const float dv = s.dd[0][g][c] + s.dd[1][g][c] + denseb[c];
        g_feat_buf[(long)(grp0 + g) * C_ + c] = fmaxf(pv, 0.f) + fmaxf(dv, 0.f);
    }
}

// ============================================================================
// K3: MLP on tensor cores, cp.async double-buffered weight pipeline.
// (round-13 version, unchanged — 184 us measured)
// ============================================================================
constexpr int OFF_X0  = 0;
constexpr int OFF_X1  = 13312;
constexpr int OFF_LN  = 26624;
constexpr int OFF_H   = OFF_LN + 2 * 32 * P1;
constexpr int MLP_WORDS = OFF_H + 2 * 32 * P2;

__global__ void __launch_bounds__(MT_, 1) mlp_kernel(
    const float* __restrict__ fc1b, const float* __restrict__ fc2b,
    const float* __restrict__ n2g, const float* __restrict__ n2b,
    float* __restrict__ out) {
    unsigned* sm = reinterpret_cast<unsigned*>(dynsm);
    unsigned* X[2] = {sm + OFF_X0, sm + OFF_X1};
    unsigned* LN0 = sm + OFF_LN;
    unsigned* LN1 = LN0 + 32 * P1;
    unsigned* H0  = sm + OFF_H;
    unsigned* H1  = H0 + 32 * P2;
    const unsigned xaddr[2] = {smem_u32(X[0]), smem_u32(X[1])};
    const int t = threadIdx.x;
    const int w = t >> 5, lane = t & 31;
    const int lp = lane >> 2, lq = lane & 3;
    const long row0 = (long)blockIdx.x * MR;

    {
        const uint4* src = reinterpret_cast<const uint4*>(g_w1);
        for (int i = t; i < 3328; i += MT_) cp16(xaddr[0] + i * 16, src + i);
        CP_COMMIT();
    }

    for (int i = t; i < 1024; i += MT_) {
        const int part = i >> 9, rr = (i >> 4) & 31, wd = i & 15;
        (part ? LN1 : LN0)[rr * P1 + 128 + wd] = 0u;
    }
    {
        const int part = t >> 8, rr = (t >> 3) & 31, wd = t & 7;
        (part ? H1 : H0)[rr * P2 + 256 + wd] = 0u;
    }

    for (int rr = 0; rr < 2; ++rr) {
        const int r = w + 16 * rr;
        const float2* frow = reinterpret_cast<const float2*>(g_feat_buf + (row0 + r) * C_);
        float2 v[4];
        float sum = 0.f;
#pragma unroll
        for (int k = 0; k < 4; ++k) { v[k] = frow[lane + 32 * k]; sum += v[k].x + v[k].y; }
#pragma unroll
        for (int o = 16; o; o >>= 1) sum += __shfl_xor_sync(FULL, sum, o);
        const float m = sum * (1.f / C_);
        float qv = 0.f;
#pragma unroll
        for (int k = 0; k < 4; ++k) {
            const float dx = v[k].x - m, dy = v[k].y - m;
            qv += dx * dx + dy * dy;
        }
#pragma unroll
        for (int o = 16; o; o >>= 1) qv += __shfl_xor_sync(FULL, qv, o);
        const float rs = rsqrtf(qv * (1.f / C_) + 1e-3f);
#pragma unroll
        for (int k = 0; k < 4; ++k) {
            const int wi = lane + 32 * k;
            const float2 gg = reinterpret_cast<const float2*>(n2g)[wi];
            const float2 bb = reinterpret_cast<const float2*>(n2b)[wi];
            const float x0 = (v[k].x - m) * rs * gg.x + bb.x;
            const float x1 = (v[k].y - m) * rs * gg.y + bb.y;
            const __nv_bfloat16 h0 = __float2bfloat16(x0), h1 = __float2bfloat16(x1);
            LN0[r * P1 + wi] = (unsigned)__bfloat16_as_ushort(h0) |
                               ((unsigned)__bfloat16_as_ushort(h1) << 16);
            LN1[r * P1 + wi] = bf16pair(x0 - __bfloat162float(h0), x1 - __bfloat162float(h1));
        }
    }
    __syncthreads();

    float cfr[2][4][4];
#pragma unroll
    for (int mt = 0; mt < 2; ++mt)
#pragma unroll
        for (int j = 0; j < 4; ++j)
#pragma unroll
            for (int e = 0; e < 4; ++e) cfr[mt][j][e] = 0.f;

    for (int p = 0; p < 12; ++p) {
        {
            const uint4* src = (p + 1 < 12)
                ? reinterpret_cast<const uint4*>(g_w1 + (long)(p + 1) * 13312)
                : reinterpret_cast<const uint4*>(g_w2);
            const unsigned dsta = xaddr[(p + 1) & 1];
            for (int i = t; i < 3328; i += MT_) cp16(dsta + i * 16, src + i);
            CP_COMMIT();
        }
        CP_WAIT1();
        __syncthreads();
        const unsigned* BBF = X[p & 1];
        const int c = p >> 1;
        if ((p & 1) == 0) {
#pragma unroll
            for (int ks = 0; ks < 3; ++ks) {
                const int ko = c * 24 + ks * 8 + lq;
                const int kb = ks * 8 + lq;
                unsigned ah[2][4], al[2][4];
#pragma unroll
                for (int mt = 0; mt < 2; ++mt) {
                    const int r0 = (mt * 16 + lp) * P1;
                    ah[mt][0] = LN0[r0 + ko];     ah[mt][1] = LN0[r0 + 8 * P1 + ko];
                    ah[mt][2] = LN0[r0 + ko + 4]; ah[mt][3] = LN0[r0 + 8 * P1 + ko + 4];
                    al[mt][0] = LN1[r0 + ko];     al[mt][1] = LN1[r0 + 8 * P1 + ko];
                    al[mt][2] = LN1[r0 + ko + 4]; al[mt][3] = LN1[r0 + 8 * P1 + ko + 4];
                }
#pragma unroll
                for (int j = 0; j < 4; ++j) {
                    const int nr = (w * 32 + j * 8 + lp) * AP;
                    const unsigned b0 = BBF[nr + kb], b1 = BBF[nr + kb + 4];
#pragma unroll
                    for (int mt = 0; mt < 2; ++mt) {
                        mma16816(cfr[mt][j], ah[mt], b0, b1);
                        mma16816(cfr[mt][j], al[mt], b0, b1);
                    }
                }
            }
        } else {
#pragma unroll
            for (int ks = 0; ks < 3; ++ks) {
                const int ko = c * 24 + ks * 8 + lq;
                const int kb = ks * 8 + lq;
                unsigned ah[2][4];
#pragma unroll
                for (int mt = 0; mt < 2; ++mt) {
                    const int r0 = (mt * 16 + lp) * P1;
                    ah[mt][0] = LN0[r0 + ko];     ah[mt][1] = LN0[r0 + 8 * P1 + ko];
                    ah[mt][2] = LN0[r0 + ko + 4]; ah[mt][3] = LN0[r0 + 8 * P1 + ko + 4];
                }
#pragma unroll
                for (int j = 0; j < 4; ++j) {
                    const int nr = (w * 32 + j * 8 + lp) * AP;
                    const unsigned b0 = BBF[nr + kb], b1 = BBF[nr + kb + 4];
#pragma unroll
                    for (int mt = 0; mt < 2; ++mt)
                        mma16816(cfr[mt][j], ah[mt], b0, b1);
                }
            }
        }
        __syncthreads();
    }

#pragma unroll
    for (int mt = 0; mt < 2; ++mt)
#pragma unroll
    for (int j = 0; j < 4; ++j) {
        const float2 bj = *reinterpret_cast<const float2*>(fc1b + w * 32 + j * 8 + 2 * lq);
        const int wd = w * 16 + j * 4 + lq;
        {
            const int row = mt * 16 + lp;
            const float v0 = fmaxf(cfr[mt][j][0] + bj.x, 0.f);
            const float v1 = fmaxf(cfr[mt][j][1] + bj.y, 0.f);
            const __nv_bfloat16 h0 = __float2bfloat16(v0), h1 = __float2bfloat16(v1);
            H0[row * P2 + wd] = (unsigned)__bfloat16_as_ushort(h0) |
                                ((unsigned)__bfloat16_as_ushort(h1) << 16);
            H1[row * P2 + wd] = bf16pair(v0 - __bfloat162float(h0), v1 - __bfloat162float(h1));
        }
        {
            const int row = mt * 16 + lp + 8;
            const float v0 = fmaxf(cfr[mt][j][2] + bj.x, 0.f);
            const float v1 = fmaxf(cfr[mt][j][3] + bj.y, 0.f);
            const __nv_bfloat16 h0 = __float2bfloat16(v0), h1 = __float2bfloat16(v1);
            H0[row * P2 + wd] = (unsigned)__bfloat16_as_ushort(h0) |
                                ((unsigned)__bfloat16_as_ushort(h1) << 16);
            H1[row * P2 + wd] = bf16pair(v0 - __bfloat162float(h0), v1 - __bfloat162float(h1));
        }
    }
    __syncthreads();

    float c2[2][2][4];
#pragma unroll
    for (int mt = 0; mt < 2; ++mt)
#pragma unroll
        for (int j = 0; j < 2; ++j)
#pragma unroll
            for (int e = 0; e < 4; ++e) c2[mt][j][e] = 0.f;

    for (int c = 0; c < 11; ++c) {
        if (c + 1 < 11) {
            const uint4* src = reinterpret_cast<const uint4*>(g_w2 + (long)(c + 1) * 13312);
            const unsigned dsta = xaddr[(c + 1) & 1];
            for (int i = t; i < 3328; i += MT_) cp16(dsta + i * 16, src + i);
            CP_COMMIT();
            CP_WAIT1();
        } else {
            CP_WAIT0();
        }
        __syncthreads();
        const unsigned* BBF = X[c & 1];
#pragma unroll
        for (int ks = 0; ks < 3; ++ks) {
            const int ko = c * 24 + ks * 8 + lq;
            const int kb = ks * 8 + lq;
            unsigned ah[2][4], al[2][4];
#pragma unroll
            for (int mt = 0; mt < 2; ++mt) {
                const int r0 = (mt * 16 + lp) * P2;
                ah[mt][0] = H0[r0 + ko];     ah[mt][1] = H0[r0 + 8 * P2 + ko];
                ah[mt][2] = H0[r0 + ko + 4]; ah[mt][3] = H0[r0 + 8 * P2 + ko + 4];
                al[mt][0] = H1[r0 + ko];     al[mt][1] = H1[r0 + 8 * P2 + ko];
                al[mt][2] = H1[r0 + ko + 4]; al[mt][3] = H1[r0 + 8 * P2 + ko + 4];
            }
#pragma unroll
            for (int j = 0; j < 2; ++j) {
                const int nr = (w * 16 + j * 8 + lp) * AP;
                const unsigned bh0 = BBF[nr + kb], bh1 = BBF[nr + kb + 4];
                const unsigned bl0 = BBF[6656 + nr + kb], bl1 = BBF[6656 + nr + kb + 4];
#pragma unroll
                for (int mt = 0; mt < 2; ++mt) {
                    mma16816(c2[mt][j], ah[mt], bh0, bh1);
                    mma16816(c2[mt][j], al[mt], bh0, bh1);
                    mma16816(c2[mt][j], ah[mt], bl0, bl1);
                }
            }
        }
        __syncthreads();
    }

#pragma unroll
    for (int mt = 0; mt < 2; ++mt)
#pragma unroll
    for (int j = 0; j < 2; ++j) {
        const int col = w * 16 + j * 8 + 2 * lq;
        const float2 bj = *reinterpret_cast<const float2*>(fc2b + col);
        {
            const long row = row0 + mt * 16 + lp;
            const float2 res = *reinterpret_cast<const float2*>(g_feat_buf + row * C_ + col);
            float2 o;
            o.x = c2[mt][j][0] + bj.x + res.x;
            o.y = c2[mt][j][1] + bj.y + res.y;
            *reinterpret_cast<float2*>(out + row * C_ + col) = o;
        }
        {
            const long row = row0 + mt * 16 + lp + 8;
            const float2 res = *reinterpret_cast<const float2*>(g_feat_buf + row * C_ + col);
            float2 o;
            o.x = c2[mt][j][2] + bj.x + res.x;
            o.y = c2[mt][j][3] + bj.y + res.y;
            *reinterpret_cast<float2*>(out + row * C_ + col) = o;
        }
    }
}

// ============================================================================
extern "C" void kernel_launch(void* const* d_in, const int* in_sizes, int n_in,
                              void* d_out, int out_size) {
    const float* xyz    = (const float*)d_in[0];
    const float* nxyz   = (const float*)d_in[1];
    const float* featin = (const float*)d_in[2];
    const float* wqkv   = (const float*)d_in[3];
    const float* projw  = (const float*)d_in[4];
    const float* projb  = (const float*)d_in[5];
    const float* densew = (const float*)d_in[6];
    const float* denseb = (const float*)d_in[7];
    const float* fc1w   = (const float*)d_in[8];
    const float* fc1b   = (const float*)d_in[9];
    const float* fc2w   = (const float*)d_in[10];
    const float* fc2b   = (const float*)d_in[11];
    const float* n1g    = (const float*)d_in[12];
    const float* n1b    = (const float*)d_in[13];
    const float* n2g    = (const float*)d_in[14];
    const float* n2b    = (const float*)d_in[15];
    float* out = (float*)d_out;

    (void)in_sizes; (void)n_in; (void)out_size;

    const int knn_smem  = N_ * (int)sizeof(float4);            // 64 KB
    const int attn_smem = (int)sizeof(SmemAll);                // ~196 KB
    const int mlp_smem  = MLP_WORDS * 4;                       // ~218 KB
    cudaFuncSetAttribute(knn_kernel, cudaFuncAttributeMaxDynamicSharedMemorySize, knn_smem);
    cudaFuncSetAttribute(attn_kernel, cudaFuncAttributeMaxDynamicSharedMemorySize, attn_smem);
    cudaFuncSetAttribute(mlp_kernel, cudaFuncAttributeMaxDynamicSharedMemorySize, mlp_smem);

    prep_kernel<<<312, 512>>>(wqkv, fc1w, fc2w);
    knn_kernel<<<dim3(NP_ / 8, B_), 256, knn_smem>>>(xyz, nxyz);
    attn_kernel<<<B_ * NP_ / G_, T_, attn_smem>>>(xyz, nxyz, featin, wqkv, projw, projb,
                                                  densew, denseb, n1g, n1b);
    mlp_kernel<<<B_ * NP_ / MR, MT_, mlp_smem>>>(fc1b, fc2b, n2g, n2b, out);
}

// round 16
// speedup vs baseline: 1.1555x; 1.0419x over previous
#include <cuda_runtime.h>
#include <cuda_bf16.h>
#include <cstdint>

typedef unsigned long long ull;
#define FULL 0xffffffffu

constexpr int B_  = 16;
constexpr int N_  = 4096;
constexpr int NP_ = 1024;
constexpr int K_  = 32;
constexpr int CIN = 128;
constexpr int CG  = 131;   // 3 + 128
constexpr int C_  = 256;
constexpr int H_  = 4;
constexpr int D_  = 64;
constexpr int TC  = 768;   // 3*C
constexpr int G_  = 4;     // groups per attn block (M = 128 rows)
constexpr int GP  = 34;    // per-group sub-pitch (floats) in xsT row
constexpr int XP  = 138;   // xsT row pitch (floats)
constexpr int T_  = 512;   // attn threads
constexpr int KC  = 48;    // K-chunk for mma (AP=26 conflict-free pattern)
constexpr int AP  = 26;    // A/B smem row pitch in 32-bit words
constexpr int MR  = 32;    // mlp rows per block (2 m-tiles)
constexpr int MT_ = 512;   // mlp threads
constexpr int P1  = 154;   // lnPk pitch words (154 mod 32 == 26)
constexpr int P2  = 282;   // hPk pitch words  (282 mod 32 == 26)

// scratch (device globals: allocation-free rule; zero-initialized)
__device__ int   g_idx_buf[B_ * NP_ * K_];
__device__ float g_feat_buf[B_ * NP_ * C_];
// weights as bf16 hi/lo, PRE-PITCHED [chunk][part][n][26 words] (words 24,25 = 0)
__device__ __align__(16) unsigned g_wq[3 * 2 * 256 * 26];
__device__ __align__(16) unsigned g_w1[6 * 2 * 512 * 26];
__device__ __align__(16) unsigned g_w2[11 * 2 * 256 * 26];

extern __shared__ __align__(16) unsigned char dynsm[];

// ---------------- packed f32x2 helpers
__device__ __forceinline__ ull pk2(float a, float b) {
    ull r;
    asm("mov.b64 %0, {%1,%2};" : "=l"(r) : "f"(a), "f"(b));
    return r;
}
__device__ __forceinline__ void upk2(ull v, float& a, float& b) {
    asm("mov.b64 {%0,%1}, %2;" : "=f"(a), "=f"(b) : "l"(v));
}
__device__ __forceinline__ void fma2(ull& d, ull a, ull b) {
    asm("fma.rn.f32x2 %0, %1, %2, %3;" : "=l"(d) : "l"(a), "l"(b), "l"(d));
}

// ---------------- warp mma m16n8k16 bf16 (base PTX, works at compute_103)
__device__ __forceinline__ void mma16816(float* d, const unsigned* a, unsigned b0, unsigned b1) {
    asm volatile(
        "mma.sync.aligned.m16n8k16.row.col.f32.bf16.bf16.f32 "
        "{%0,%1,%2,%3}, {%4,%5,%6,%7}, {%8,%9}, {%0,%1,%2,%3};"
        : "+f"(d[0]), "+f"(d[1]), "+f"(d[2]), "+f"(d[3])
        : "r"(a[0]), "r"(a[1]), "r"(a[2]), "r"(a[3]), "r"(b0), "r"(b1));
}
__device__ __forceinline__ unsigned bf16pair(float x0, float x1) {
    const __nv_bfloat16 h0 = __float2bfloat16(x0), h1 = __float2bfloat16(x1);
    return (unsigned)__bfloat16_as_ushort(h0) | ((unsigned)__bfloat16_as_ushort(h1) << 16);
}
__device__ __forceinline__ unsigned smem_u32(const void* p) {
    unsigned a;
    asm("{ .reg .u64 t; cvta.to.shared.u64 t, %1; cvt.u32.u64 %0, t; }" : "=r"(a) : "l"(p));
    return a;
}
// ---------------- cp.async helpers (base PTX sm_80+)
__device__ __forceinline__ void cp16(unsigned smaddr, const void* gptr) {
    asm volatile("cp.async.cg.shared.global [%0], [%1], 16;" :: "r"(smaddr), "l"(gptr));
}
#define CP_COMMIT() asm volatile("cp.async.commit_group;" ::: "memory")
#define CP_WAIT1()  asm volatile("cp.async.wait_group 1;" ::: "memory")
#define CP_WAIT0()  asm volatile("cp.async.wait_group 0;" ::: "memory")

// monotone float -> uint map (order preserving)
__device__ __forceinline__ unsigned fmapu(float f) {
    unsigned u = __float_as_uint(f);
    return (u & 0x80000000u) ? ~u : (u | 0x80000000u);
}

// ============================================================================
// K0: prep — convert Wq, fc1w, fc2w to bf16 hi/lo pre-pitched layouts.
// ============================================================================
__global__ void __launch_bounds__(512) prep_kernel(const float* __restrict__ wqkv,
                                                   const float* __restrict__ fc1w,
                                                   const float* __restrict__ fc2w) {
    const int idx = blockIdx.x * 512 + threadIdx.x;
    if (idx < 18432) {                       // Wq: 3 chunks x 256 n x 24 j
        const int c = idx / 6144, rem = idx % 6144;
        const int n = rem / 24, j = rem % 24;
        const int k = c * KC + 2 * j;
        const float x0 = (k < CG) ? wqkv[(long)k * TC + n] : 0.f;
        const float x1 = (k + 1 < CG) ? wqkv[(long)(k + 1) * TC + n] : 0.f;
        const __nv_bfloat16 h0 = __float2bfloat16(x0), h1 = __float2bfloat16(x1);
        g_wq[(c * 2 + 0) * 6656 + n * 26 + j] = bf16pair(x0, x1);
        g_wq[(c * 2 + 1) * 6656 + n * 26 + j] =
            bf16pair(x0 - __bfloat162float(h0), x1 - __bfloat162float(h1));
    } else if (idx < 92160) {                // fc1w: 6 chunks x 512 n x 24 j
        const int i = idx - 18432;
        const int c = i / 12288, rem = i % 12288;
        const int n = rem / 24, j = rem % 24;
        const int k = c * KC + 2 * j;
        const float x0 = (k < C_) ? fc1w[(long)k * (2 * C_) + n] : 0.f;
        const float x1 = (k + 1 < C_) ? fc1w[(long)(k + 1) * (2 * C_) + n] : 0.f;
        const __nv_bfloat16 h0 = __float2bfloat16(x0), h1 = __float2bfloat16(x1);
        g_w1[(c * 2 + 0) * 13312 + n * 26 + j] = bf16pair(x0, x1);
        g_w1[(c * 2 + 1) * 13312 + n * 26 + j] =
            bf16pair(x0 - __bfloat162float(h0), x1 - __bfloat162float(h1));
    } else if (idx < 159744) {               // fc2w: 11 chunks x 256 n x 24 j
        const int i = idx - 92160;
        const int c = i / 6144, rem = i % 6144;
        const int n = rem / 24, j = rem % 24;
        const int k = c * KC + 2 * j;
        const float x0 = (k < 2 * C_) ? fc2w[(long)k * C_ + n] : 0.f;
        const float x1 = (k + 1 < 2 * C_) ? fc2w[(long)(k + 1) * C_ + n] : 0.f;
        const __nv_bfloat16 h0 = __float2bfloat16(x0), h1 = __float2bfloat16(x1);
        g_w2[(c * 2 + 0) * 6656 + n * 26 + j] = bf16pair(x0, x1);
        g_w2[(c * 2 + 1) * 6656 + n * 26 + j] =
            bf16pair(x0 - __bfloat162float(h0), x1 - __bfloat162float(h1));
    }
}

// ============================================================================
// K1: KNN. 512 threads = 16 warps/block (3 blocks/SM -> 48 warps/SM).
// One warp per query, max-replacement top-32 (set-only), REDUX max.
// ============================================================================
__global__ void __launch_bounds__(512) knn_kernel(const float* __restrict__ xyz,
                                                  const float* __restrict__ nxyz) {
    float4* pts = reinterpret_cast<float4*>(dynsm);
    const int b = blockIdx.y;
    const float* xb = xyz + (long)b * N_ * 3;
    for (int j = threadIdx.x; j < N_; j += 512) {
        float x = xb[j * 3 + 0], y = xb[j * 3 + 1], z = xb[j * 3 + 2];
        pts[j] = make_float4(x, y, z, x * x + y * y + z * z);
    }
    __syncthreads();

    const int warp = threadIdx.x >> 5, lane = threadIdx.x & 31;
    const int p = blockIdx.x * 16 + warp;
    const float* q = nxyz + ((long)b * NP_ + p) * 3;
    const float qx = q[0], qy = q[1], qz = q[2];

    float4 c0 = pts[lane];
    unsigned bestU = fmapu(c0.w - 2.f * (qx * c0.x + qy * c0.y + qz * c0.z));
    int besti = lane;
    unsigned curmaxU = __reduce_max_sync(FULL, bestU);

    for (int j0 = K_; j0 < N_; j0 += K_) {
        float4 c = pts[j0 + lane];
        const unsigned dm = fmapu(c.w - 2.f * (qx * c.x + qy * c.y + qz * c.z));
        unsigned mset = __ballot_sync(FULL, dm < curmaxU);
        while (mset) {
            int src = __ffs(mset) - 1;
            mset &= mset - 1;
            const unsigned cdU = __shfl_sync(FULL, dm, src);
            if (cdU < curmaxU) {
                unsigned vict = __ballot_sync(FULL, bestU == curmaxU);
                int vl = __ffs(vict) - 1;
                if (lane == vl) { bestU = cdU; besti = j0 + src; }
                curmaxU = __reduce_max_sync(FULL, bestU);
            }
        }
    }
    g_idx_buf[((long)b * NP_ + p) * K_ + lane] = besti;
}

// ============================================================================
// K2: attn — round-15 structure + paired z-phase loads + deeper epilogue
// unrolls.
// ============================================================================
struct __align__(16) SmemAll {
    unsigned Abf[2][128][AP];
    unsigned Bbf[2][256][AP];
    float xsT[CG][XP];
    float pad0[2];
    float qm[G_][C_];
    float gmax[G_][132];
    float z[G_][H_][132];
    float y[G_][H_][132];
    float attnw[G_][H_][K_];
    float sat[G_][C_];
    float pp[2][G_][C_];
    float dd[2][G_][C_];
    float n1gS[132];
    float n1bS[132];
    int   nidx[G_][K_];
    float q3[G_][4];
};

__global__ void __launch_bounds__(T_, 1) attn_kernel(
    const float* __restrict__ xyz, const float* __restrict__ nxyz,
    const float* __restrict__ featin, const float* __restrict__ wqkv,
    const float* __restrict__ projw, const float* __restrict__ projb,
    const float* __restrict__ densew, const float* __restrict__ denseb,
    const float* __restrict__ n1g, const float* __restrict__ n1b) {
    SmemAll& s = *reinterpret_cast<SmemAll*>(dynsm);
    const int t = threadIdx.x;
    const int w = t >> 5, lane = t & 31;
    const int grp0 = blockIdx.x * G_;
    const int b = grp0 >> 10, p0 = grp0 & 1023;

    // prefetch chunk-0 B (both parts) — drains under gather + LN
    {
        const unsigned ba = smem_u32(&s.Bbf[0][0][0]);
        const uint4* src = reinterpret_cast<const uint4*>(g_wq);
        for (int i = t; i < 3328; i += T_) cp16(ba + i * 16, src + i);
        CP_COMMIT();
    }

    if (t < G_ * K_) {
        int g = t >> 5, r = t & 31;
        s.nidx[g][r] = g_idx_buf[(long)(grp0 + g) * K_ + r];
    }
    if (t < G_ * 3) {
        int g = t / 3, c = t % 3;
        s.q3[g][c] = nxyz[((long)b * NP_ + p0 + g) * 3 + c];
    }
    if (t >= 128 && t < 128 + CG) {
        s.n1gS[t - 128] = n1g[t - 128];
        s.n1bS[t - 128] = n1b[t - 128];
    }
    __syncthreads();

    if (t < G_ * K_) {
        int g = t >> 5, r = t & 31;
        int j = s.nidx[g][r];
        const float* xp = xyz + ((long)b * N_ + j) * 3;
        s.xsT[0][g * GP + r] = xp[0] - s.q3[g][0];
        s.xsT[1][g * GP + r] = xp[1] - s.q3[g][1];
        s.xsT[2][g * GP + r] = xp[2] - s.q3[g][2];
    }
    // gather features as float4: 4096 vec4 elements
    for (int e = t; e < G_ * K_ * (CIN / 4); e += T_) {
        const int g = e >> 10, r = (e >> 5) & 31, i4 = e & 31;
        const float4 v = *reinterpret_cast<const float4*>(
            featin + ((long)b * N_ + s.nidx[g][r]) * CIN + 4 * i4);
        const int col = g * GP + r;
        s.xsT[3 + 4 * i4 + 0][col] = v.x;
        s.xsT[3 + 4 * i4 + 1][col] = v.y;
        s.xsT[3 + 4 * i4 + 2][col] = v.z;
        s.xsT[3 + 4 * i4 + 3][col] = v.w;
    }
    __syncthreads();

    for (int e = t; e < G_ * CG; e += T_) {
        int g = e / CG, i = e - g * CG;
        float m = s.xsT[i][g * GP];
#pragma unroll
        for (int r = 1; r < K_; ++r) m = fmaxf(m, s.xsT[i][g * GP + r]);
        s.gmax[g][i] = m;
    }
    __syncthreads();

    for (int k = 0; k < 8; ++k) {
        const int row = w + 16 * k;
        const int g = row >> 5, r = row & 31;
        float v[5];
        int kn = 0;
        float sum = 0.f;
        for (int ii = lane; ii < CG; ii += 32) { v[kn] = s.xsT[ii][g * GP + r]; sum += v[kn]; ++kn; }
#pragma unroll
        for (int o = 16; o; o >>= 1) sum += __shfl_xor_sync(FULL, sum, o);
        const float m = sum * (1.f / CG);
        float qv = 0.f;
        for (int kk = 0; kk < kn; ++kk) { float d = v[kk] - m; qv += d * d; }
#pragma unroll
        for (int o = 16; o; o >>= 1) qv += __shfl_xor_sync(FULL, qv, o);
        const float rs = rsqrtf(qv * (1.f / CG) + 1e-3f);
        kn = 0;
        for (int ii = lane; ii < CG; ii += 32) {
            s.xsT[ii][g * GP + r] = (v[kn] - m) * rs * s.n1gS[ii] + s.n1bS[ii];
            ++kn;
        }
    }
    __syncthreads();

    const int gq = w & 3;
    const int mbase = 32 * gq;
    const int nbase = (w >> 2) * 64;
    const int lp = lane >> 2, lq = lane & 3;
    float cfr[2][8][4];
#pragma unroll
    for (int mt = 0; mt < 2; ++mt)
#pragma unroll
        for (int j = 0; j < 8; ++j)
#pragma unroll
            for (int e = 0; e < 4; ++e) cfr[mt][j][e] = 0.f;

    const unsigned* A0 = &s.Abf[0][0][0];
    const unsigned* A1 = &s.Abf[1][0][0];
    const unsigned* B0 = &s.Bbf[0][0][0];
    const unsigned* B1 = &s.Bbf[1][0][0];

    for (int c = 0; c < 3; ++c) {
        if (c == 0) {
            // chunk-0 A convert with all 512 threads (B arrives via cp.async)
            const int mq = t & 127, qd = t >> 7;
            const int colx = (mq >> 5) * GP + (mq & 31);
#pragma unroll
            for (int jj = 0; jj < 6; ++jj) {
                const int j = qd * 6 + jj;
                const int k = 2 * j;
                const float x0 = s.xsT[k][colx];
                const float x1 = s.xsT[k + 1][colx];
                const __nv_bfloat16 h0 = __float2bfloat16(x0), h1 = __float2bfloat16(x1);
                s.Abf[0][mq][j] = (unsigned)__bfloat16_as_ushort(h0) |
                                  ((unsigned)__bfloat16_as_ushort(h1) << 16);
                s.Abf[1][mq][j] = bf16pair(x0 - __bfloat162float(h0), x1 - __bfloat162float(h1));
            }
            CP_WAIT0();
        } else if (t < 256) {
            // warp-split prologue: warps 0-7 convert A
            const int mq = t & 127, qd = t >> 7;
            const int colx = (mq >> 5) * GP + (mq & 31);
#pragma unroll
            for (int jj = 0; jj < 12; ++jj) {
                const int j = qd * 12 + jj;
                const int k = c * KC + 2 * j;
                const float x0 = (k < CG) ? s.xsT[k][colx] : 0.f;
                const float x1 = (k + 1 < CG) ? s.xsT[k + 1][colx] : 0.f;
                const __nv_bfloat16 h0 = __float2bfloat16(x0), h1 = __float2bfloat16(x1);
                s.Abf[0][mq][j] = (unsigned)__bfloat16_as_ushort(h0) |
                                  ((unsigned)__bfloat16_as_ushort(h1) << 16);
                s.Abf[1][mq][j] = bf16pair(x0 - __bfloat162float(h0), x1 - __bfloat162float(h1));
            }
        } else {
            // warps 8-15 stream B (both parts, contiguous, pre-pitched)
            const uint4* src = reinterpret_cast<const uint4*>(g_wq + (long)c * 13312);
            uint4* dst = reinterpret_cast<uint4*>(&s.Bbf[0][0][0]);
#pragma unroll
            for (int i = 0; i < 13; ++i) dst[(t - 256) + 256 * i] = src[(t - 256) + 256 * i];
        }
        __syncthreads();

#pragma unroll
        for (int ks = 0; ks < 3; ++ks) {
            const int ko = ks * 8 + lq;
            unsigned ah[2][4], al[2][4];
#pragma unroll
            for (int mt = 0; mt < 2; ++mt) {
                const int r0 = (mbase + mt * 16 + lp) * AP;
                const int r8 = r0 + 8 * AP;
                ah[mt][0] = A0[r0 + ko];     ah[mt][1] = A0[r8 + ko];
                ah[mt][2] = A0[r0 + ko + 4]; ah[mt][3] = A0[r8 + ko + 4];
                al[mt][0] = A1[r0 + ko];     al[mt][1] = A1[r8 + ko];
                al[mt][2] = A1[r0 + ko + 4]; al[mt][3] = A1[r8 + ko + 4];
            }
#pragma unroll
            for (int j = 0; j < 8; ++j) {
                const int nr = (nbase + j * 8 + lp) * AP;
                const unsigned bh0 = B0[nr + ko], bh1 = B0[nr + ko + 4];
                const unsigned bl0 = B1[nr + ko], bl1 = B1[nr + ko + 4];
#pragma unroll
                for (int mt = 0; mt < 2; ++mt) {
                    mma16816(cfr[mt][j], ah[mt], bh0, bh1);
                    mma16816(cfr[mt][j], ah[mt], bl0, bl1);
                    mma16816(cfr[mt][j], al[mt], bh0, bh1);
                }
            }
        }
        __syncthreads();
    }

#pragma unroll
    for (int j = 0; j < 8; ++j) {
        float ve = fmaxf(fmaxf(cfr[0][j][0], cfr[0][j][2]), fmaxf(cfr[1][j][0], cfr[1][j][2]));
        float vo = fmaxf(fmaxf(cfr[0][j][1], cfr[0][j][3]), fmaxf(cfr[1][j][1], cfr[1][j][3]));
#pragma unroll
        for (int o = 4; o <= 16; o <<= 1) {
            ve = fmaxf(ve, __shfl_xor_sync(FULL, ve, o));
            vo = fmaxf(vo, __shfl_xor_sync(FULL, vo, o));
        }
        if (lane < 4) {
            s.qm[gq][nbase + j * 8 + 2 * lane]     = ve;
            s.qm[gq][nbase + j * 8 + 2 * lane + 1] = vo;
        }
    }
    __syncthreads();

    // ---- z[g][h][i]: paired loads (2 i's per step -> 4 LDG.128 in flight)
    {
        float4 qa[G_], qb[G_];
#pragma unroll
        for (int g = 0; g < G_; ++g) {
            qa[g] = reinterpret_cast<const float4*>(s.qm[g])[lane];
            qb[g] = reinterpret_cast<const float4*>(s.qm[g])[32 + lane];
        }
        for (int i = w; i < CG; i += 32) {
            const int i2 = i + 16;
            const bool has2 = (i2 < CG);
            const float4* wrA = reinterpret_cast<const float4*>(wqkv + (long)i * TC + C_);
            const float4* wrB = reinterpret_cast<const float4*>(
                wqkv + (long)(has2 ? i2 : i) * TC + C_);
            const float4 a0 = wrA[lane], a1 = wrA[32 + lane];
            const float4 b0v = wrB[lane], b1v = wrB[32 + lane];
            float sA0[G_], sA1[G_], sB0[G_], sB1[G_];
#pragma unroll
            for (int g = 0; g < G_; ++g) {
                sA0[g] = a0.x * qa[g].x + a0.y * qa[g].y + a0.z * qa[g].z + a0.w * qa[g].w;
                sA1[g] = a1.x * qb[g].x + a1.y * qb[g].y + a1.z * qb[g].z + a1.w * qb[g].w;
                sB0[g] = b0v.x * qa[g].x + b0v.y * qa[g].y + b0v.z * qa[g].z + b0v.w * qa[g].w;
                sB1[g] = b1v.x * qb[g].x + b1v.y * qb[g].y + b1v.z * qb[g].z + b1v.w * qb[g].w;
            }
#pragma unroll
            for (int o = 8; o; o >>= 1) {
#pragma unroll
                for (int g = 0; g < G_; ++g) {
                    sA0[g] += __shfl_xor_sync(FULL, sA0[g], o);
                    sA1[g] += __shfl_xor_sync(FULL, sA1[g], o);
                    sB0[g] += __shfl_xor_sync(FULL, sB0[g], o);
                    sB1[g] += __shfl_xor_sync(FULL, sB1[g], o);
                }
            }
            if ((lane & 15) == 0) {
                const int h0 = lane >> 4;
#pragma unroll
                for (int g = 0; g < G_; ++g) {
                    s.z[g][h0][i]     = sA0[g];
                    s.z[g][h0 + 2][i] = sA1[g];
                    if (has2) {
                        s.z[g][h0][i2]     = sB0[g];
                        s.z[g][h0 + 2][i2] = sB1[g];
                    }
                }
            }
        }
    }
    __syncthreads();

    {
        const int g = w >> 2, h = w & 3, r = lane;
        float a = 0.f;
#pragma unroll 8
        for (int i = 0; i < CG; ++i) a += s.xsT[i][g * GP + r] * s.z[g][h][i];
        a *= 0.0625f;
        float mx = a;
#pragma unroll
        for (int o = 16; o; o >>= 1) mx = fmaxf(mx, __shfl_xor_sync(FULL, mx, o));
        const float e = expf(a - mx);
        float ss = e;
#pragma unroll
        for (int o = 16; o; o >>= 1) ss += __shfl_xor_sync(FULL, ss, o);
        s.attnw[g][h][r] = e / ss;
    }
    __syncthreads();

    for (int e = t; e < G_ * H_ * CG; e += T_) {
        const int i = e % CG;
        const int gh = e / CG;
        const int g = gh >> 2, h = gh & 3;
        const ull* aw = reinterpret_cast<const ull*>(s.attnw[g][h]);
        const ull* xr = reinterpret_cast<const ull*>(&s.xsT[i][g * GP]);
        ull acc = 0ull;
#pragma unroll
        for (int rp = 0; rp < 16; ++rp) fma2(acc, xr[rp], aw[rp]);
        float a, b2; upk2(acc, a, b2);
        s.y[g][h][i] = a + b2;
    }
    __syncthreads();

    // ---- sat partials: thread = (c, K-half); all 4 groups per thread
    {
        const int c = t & 255, half = t >> 8;
        const int h = c >> 6;
        const int i0 = half ? 66 : 0, i1 = half ? CG : 66;
        const float* wv = wqkv + 2 * C_ + c;
        float a0 = 0.f, a1 = 0.f, a2 = 0.f, a3 = 0.f;
#pragma unroll 16
        for (int i = i0; i < i1; ++i) {
            const float wvi = wv[(long)i * TC];
            a0 += s.y[0][h][i] * wvi;
            a1 += s.y[1][h][i] * wvi;
            a2 += s.y[2][h][i] * wvi;
            a3 += s.y[3][h][i] * wvi;
        }
        s.pp[half][0][c] = a0;
        s.pp[half][1][c] = a1;
        s.pp[half][2][c] = a2;
        s.pp[half][3][c] = a3;
    }
    __syncthreads();
    for (int e = t; e < G_ * C_; e += T_) {
        const int g = e >> 8, c = e & 255;
        s.sat[g][c] = s.pp[0][g][c] + s.pp[1][g][c];
    }
    __syncthreads();

    // ---- proj + dense partials: thread = (c, K-half); all 4 groups
    {
        const int c = t & 255, half = t >> 8;
        float p0 = 0.f, p1 = 0.f, p2 = 0.f, p3 = 0.f;
        const int pi0 = half * 128, pi1 = pi0 + 128;
        const float* wp = projw + c;
#pragma unroll 16
        for (int i = pi0; i < pi1; ++i) {
            const float wv = wp[(long)i * C_];
            p0 += s.sat[0][i] * wv;
            p1 += s.sat[1][i] * wv;
            p2 += s.sat[2][i] * wv;
            p3 += s.sat[3][i] * wv;
        }
        float d0 = 0.f, d1 = 0.f, d2 = 0.f, d3 = 0.f;
        const int di0 = half ? 66 : 0, di1 = half ? CG : 66;
        const float* wd = densew + c;
#pragma unroll 16
        for (int i = di0; i < di1; ++i) {
            const float wv = wd[(long)i * C_];
            d0 += s.gmax[0][i] * wv;
            d1 += s.gmax[1][i] * wv;
            d2 += s.gmax[2][i] * wv;
            d3 += s.gmax[3][i] * wv;
        }
        s.pp[half][0][c] = p0; s.pp[half][1][c] = p1;
        s.pp[half][2][c] = p2; s.pp[half][3][c] = p3;
        s.dd[half][0][c] = d0; s.dd[half][1][c] = d1;
        s.dd[half][2][c] = d2; s.dd[half][3][c] = d3;
    }
    __syncthreads();
    for (int e = t; e < G_ * C_; e += T_) {
        const int g = e >> 8, c = e & 255;
        const float pv = s.pp[0][g][c] + s.pp[1][g][c] + projb[c];
        const float dv = s.dd[0][g][c] + s.dd[1][g][c] + denseb[c];
        g_feat_buf[(long)(grp0 + g) * C_ + c] = fmaxf(pv, 0.f) + fmaxf(dv, 0.f);
    }
}

// ============================================================================
// K3: MLP on tensor cores, cp.async double-buffered weight pipeline.
// (round-13 version, unchanged — 184 us measured)
// ============================================================================
constexpr int OFF_X0  = 0;
constexpr int OFF_X1  = 13312;
constexpr int OFF_LN  = 26624;
constexpr int OFF_H   = OFF_LN + 2 * 32 * P1;
constexpr int MLP_WORDS = OFF_H + 2 * 32 * P2;

__global__ void __launch_bounds__(MT_, 1) mlp_kernel(
    const float* __restrict__ fc1b, const float* __restrict__ fc2b,
    const float* __restrict__ n2g, const float* __restrict__ n2b,
    float* __restrict__ out) {
    unsigned* sm = reinterpret_cast<unsigned*>(dynsm);
    unsigned* X[2] = {sm + OFF_X0, sm + OFF_X1};
    unsigned* LN0 = sm + OFF_LN;
    unsigned* LN1 = LN0 + 32 * P1;
    unsigned* H0  = sm + OFF_H;
    unsigned* H1  = H0 + 32 * P2;
    const unsigned xaddr[2] = {smem_u32(X[0]), smem_u32(X[1])};
    const int t = threadIdx.x;
    const int w = t >> 5, lane = t & 31;
    const int lp = lane >> 2, lq = lane & 3;
    const long row0 = (long)blockIdx.x * MR;

    {
        const uint4* src = reinterpret_cast<const uint4*>(g_w1);
        for (int i = t; i < 3328; i += MT_) cp16(xaddr[0] + i * 16, src + i);
        CP_COMMIT();
    }

    for (int i = t; i < 1024; i += MT_) {
        const int part = i >> 9, rr = (i >> 4) & 31, wd = i & 15;
        (part ? LN1 : LN0)[rr * P1 + 128 + wd] = 0u;
    }
    {
        const int part = t >> 8, rr = (t >> 3) & 31, wd = t & 7;
        (part ? H1 : H0)[rr * P2 + 256 + wd] = 0u;
    }

    for (int rr = 0; rr < 2; ++rr) {
        const int r = w + 16 * rr;
        const float2* frow = reinterpret_cast<const float2*>(g_feat_buf + (row0 + r) * C_);
        float2 v[4];
        float sum = 0.f;
#pragma unroll
        for (int k = 0; k < 4; ++k) { v[k] = frow[lane + 32 * k]; sum += v[k].x + v[k].y; }
#pragma unroll
        for (int o = 16; o; o >>= 1) sum += __shfl_xor_sync(FULL, sum, o);
        const float m = sum * (1.f / C_);
        float qv = 0.f;
#pragma unroll
        for (int k = 0; k < 4; ++k) {
            const float dx = v[k].x - m, dy = v[k].y - m;
            qv += dx * dx + dy * dy;
        }
#pragma unroll
        for (int o = 16; o; o >>= 1) qv += __shfl_xor_sync(FULL, qv, o);
        const float rs = rsqrtf(qv * (1.f / C_) + 1e-3f);
#pragma unroll
        for (int k = 0; k < 4; ++k) {
            const int wi = lane + 32 * k;
            const float2 gg = reinterpret_cast<const float2*>(n2g)[wi];
            const float2 bb = reinterpret_cast<const float2*>(n2b)[wi];
            const float x0 = (v[k].x - m) * rs * gg.x + bb.x;
            const float x1 = (v[k].y - m) * rs * gg.y + bb.y;
            const __nv_bfloat16 h0 = __float2bfloat16(x0), h1 = __float2bfloat16(x1);
            LN0[r * P1 + wi] = (unsigned)__bfloat16_as_ushort(h0) |
                               ((unsigned)__bfloat16_as_ushort(h1) << 16);
            LN1[r * P1 + wi] = bf16pair(x0 - __bfloat162float(h0), x1 - __bfloat162float(h1));
        }
    }
    __syncthreads();

    float cfr[2][4][4];
#pragma unroll
    for (int mt = 0; mt < 2; ++mt)
#pragma unroll
        for (int j = 0; j < 4; ++j)
#pragma unroll
            for (int e = 0; e < 4; ++e) cfr[mt][j][e] = 0.f;

    for (int p = 0; p < 12; ++p) {
        {
            const uint4* src = (p + 1 < 12)
                ? reinterpret_cast<const uint4*>(g_w1 + (long)(p + 1) * 13312)
                : reinterpret_cast<const uint4*>(g_w2);
            const unsigned dsta = xaddr[(p + 1) & 1];
            for (int i = t; i < 3328; i += MT_) cp16(dsta + i * 16, src + i);
            CP_COMMIT();
        }
        CP_WAIT1();
        __syncthreads();
        const unsigned* BBF = X[p & 1];
        const int c = p >> 1;
        if ((p & 1) == 0) {
#pragma unroll
            for (int ks = 0; ks < 3; ++ks) {
                const int ko = c * 24 + ks * 8 + lq;
                const int kb = ks * 8 + lq;
                unsigned ah[2][4], al[2][4];
#pragma unroll
                for (int mt = 0; mt < 2; ++mt) {
                    const int r0 = (mt * 16 + lp) * P1;
                    ah[mt][0] = LN0[r0 + ko];     ah[mt][1] = LN0[r0 + 8 * P1 + ko];
                    ah[mt][2] = LN0[r0 + ko + 4]; ah[mt][3] = LN0[r0 + 8 * P1 + ko + 4];
                    al[mt][0] = LN1[r0 + ko];     al[mt][1] = LN1[r0 + 8 * P1 + ko];
                    al[mt][2] = LN1[r0 + ko + 4]; al[mt][3] = LN1[r0 + 8 * P1 + ko + 4];
                }
#pragma unroll
                for (int j = 0; j < 4; ++j) {
                    const int nr = (w * 32 + j * 8 + lp) * AP;
                    const unsigned b0 = BBF[nr + kb], b1 = BBF[nr + kb + 4];
#pragma unroll
                    for (int mt = 0; mt < 2; ++mt) {
                        mma16816(cfr[mt][j], ah[mt], b0, b1);
                        mma16816(cfr[mt][j], al[mt], b0, b1);
                    }
                }
            }
        } else {
#pragma unroll
            for (int ks = 0; ks < 3; ++ks) {
                const int ko = c * 24 + ks * 8 + lq;
                const int kb = ks * 8 + lq;
                unsigned ah[2][4];
#pragma unroll
                for (int mt = 0; mt < 2; ++mt) {
                    const int r0 = (mt * 16 + lp) * P1;
                    ah[mt][0] = LN0[r0 + ko];     ah[mt][1] = LN0[r0 + 8 * P1 + ko];
                    ah[mt][2] = LN0[r0 + ko + 4]; ah[mt][3] = LN0[r0 + 8 * P1 + ko + 4];
                }
#pragma unroll
                for (int j = 0; j < 4; ++j) {
                    const int nr = (w * 32 + j * 8 + lp) * AP;
                    const unsigned b0 = BBF[nr + kb], b1 = BBF[nr + kb + 4];
#pragma unroll
                    for (int mt = 0; mt < 2; ++mt)
                        mma16816(cfr[mt][j], ah[mt], b0, b1);
                }
            }
        }
        __syncthreads();
    }

#pragma unroll
    for (int mt = 0; mt < 2; ++mt)
#pragma unroll
    for (int j = 0; j < 4; ++j) {
        const float2 bj = *reinterpret_cast<const float2*>(fc1b + w * 32 + j * 8 + 2 * lq);
        const int wd = w * 16 + j * 4 + lq;
        {
            const int row = mt * 16 + lp;
            const float v0 = fmaxf(cfr[mt][j][0] + bj.x, 0.f);
            const float v1 = fmaxf(cfr[mt][j][1] + bj.y, 0.f);
            const __nv_bfloat16 h0 = __float2bfloat16(v0), h1 = __float2bfloat16(v1);
            H0[row * P2 + wd] = (unsigned)__bfloat16_as_ushort(h0) |
                                ((unsigned)__bfloat16_as_ushort(h1) << 16);
            H1[row * P2 + wd] = bf16pair(v0 - __bfloat162float(h0), v1 - __bfloat162float(h1));
        }
        {
            const int row = mt * 16 + lp + 8;
            const float v0 = fmaxf(cfr[mt][j][2] + bj.x, 0.f);
            const float v1 = fmaxf(cfr[mt][j][3] + bj.y, 0.f);
            const __nv_bfloat16 h0 = __float2bfloat16(v0), h1 = __float2bfloat16(v1);
            H0[row * P2 + wd] = (unsigned)__bfloat16_as_ushort(h0) |
                                ((unsigned)__bfloat16_as_ushort(h1) << 16);
            H1[row * P2 + wd] = bf16pair(v0 - __bfloat162float(h0), v1 - __bfloat162float(h1));
        }
    }
    __syncthreads();

    float c2[2][2][4];
#pragma unroll
    for (int mt = 0; mt < 2; ++mt)
#pragma unroll
        for (int j = 0; j < 2; ++j)
#pragma unroll
            for (int e = 0; e < 4; ++e) c2[mt][j][e] = 0.f;

    for (int c = 0; c < 11; ++c) {
        if (c + 1 < 11) {
            const uint4* src = reinterpret_cast<const uint4*>(g_w2 + (long)(c + 1) * 13312);
            const unsigned dsta = xaddr[(c + 1) & 1];
            for (int i = t; i < 3328; i += MT_) cp16(dsta + i * 16, src + i);
            CP_COMMIT();
            CP_WAIT1();
        } else {
            CP_WAIT0();
        }
        __syncthreads();
        const unsigned* BBF = X[c & 1];
#pragma unroll
        for (int ks = 0; ks < 3; ++ks) {
            const int ko = c * 24 + ks * 8 + lq;
            const int kb = ks * 8 + lq;
            unsigned ah[2][4], al[2][4];
#pragma unroll
            for (int mt = 0; mt < 2; ++mt) {
                const int r0 = (mt * 16 + lp) * P2;
                ah[mt][0] = H0[r0 + ko];     ah[mt][1] = H0[r0 + 8 * P2 + ko];
                ah[mt][2] = H0[r0 + ko + 4]; ah[mt][3] = H0[r0 + 8 * P2 + ko + 4];
                al[mt][0] = H1[r0 + ko];     al[mt][1] = H1[r0 + 8 * P2 + ko];
                al[mt][2] = H1[r0 + ko + 4]; al[mt][3] = H1[r0 + 8 * P2 + ko + 4];
            }
#pragma unroll
            for (int j = 0; j < 2; ++j) {
                const int nr = (w * 16 + j * 8 + lp) * AP;
                const unsigned bh0 = BBF[nr + kb], bh1 = BBF[nr + kb + 4];
                const unsigned bl0 = BBF[6656 + nr + kb], bl1 = BBF[6656 + nr + kb + 4];
#pragma unroll
                for (int mt = 0; mt < 2; ++mt) {
                    mma16816(c2[mt][j], ah[mt], bh0, bh1);
                    mma16816(c2[mt][j], al[mt], bh0, bh1);
                    mma16816(c2[mt][j], ah[mt], bl0, bl1);
                }
            }
        }
        __syncthreads();
    }

#pragma unroll
    for (int mt = 0; mt < 2; ++mt)
#pragma unroll
    for (int j = 0; j < 2; ++j) {
        const int col = w * 16 + j * 8 + 2 * lq;
        const float2 bj = *reinterpret_cast<const float2*>(fc2b + col);
        {
            const long row = row0 + mt * 16 + lp;
            const float2 res = *reinterpret_cast<const float2*>(g_feat_buf + row * C_ + col);
            float2 o;
            o.x = c2[mt][j][0] + bj.x + res.x;
            o.y = c2[mt][j][1] + bj.y + res.y;
            *reinterpret_cast<float2*>(out + row * C_ + col) = o;
        }
        {
            const long row = row0 + mt * 16 + lp + 8;
            const float2 res = *reinterpret_cast<const float2*>(g_feat_buf + row * C_ + col);
            float2 o;
            o.x = c2[mt][j][2] + bj.x + res.x;
            o.y = c2[mt][j][3] + bj.y + res.y;
            *reinterpret_cast<float2*>(out + row * C_ + col) = o;
        }
    }
}

// ============================================================================
extern "C" void kernel_launch(void* const* d_in, const int* in_sizes, int n_in,
                              void* d_out, int out_size) {
    const float* xyz    = (const float*)d_in[0];
    const float* nxyz   = (const float*)d_in[1];
    const float* featin = (const float*)d_in[2];
    const float* wqkv   = (const float*)d_in[3];
    const float* projw  = (const float*)d_in[4];
    const float* projb  = (const float*)d_in[5];
    const float* densew = (const float*)d_in[6];
    const float* denseb = (const float*)d_in[7];
    const float* fc1w   = (const float*)d_in[8];
    const float* fc1b   = (const float*)d_in[9];
    const float* fc2w   = (const float*)d_in[10];
    const float* fc2b   = (const float*)d_in[11];
    const float* n1g    = (const float*)d_in[12];
    const float* n1b    = (const float*)d_in[13];
    const float* n2g    = (const float*)d_in[14];
    const float* n2b    = (const float*)d_in[15];
    float* out = (float*)d_out;

    (void)in_sizes; (void)n_in; (void)out_size;

    const int knn_smem  = N_ * (int)sizeof(float4);            // 64 KB
    const int attn_smem = (int)sizeof(SmemAll);                // ~196 KB
    const int mlp_smem  = MLP_WORDS * 4;                       // ~218 KB
    cudaFuncSetAttribute(knn_kernel, cudaFuncAttributeMaxDynamicSharedMemorySize, knn_smem);
    cudaFuncSetAttribute(attn_kernel, cudaFuncAttributeMaxDynamicSharedMemorySize, attn_smem);
    cudaFuncSetAttribute(mlp_kernel, cudaFuncAttributeMaxDynamicSharedMemorySize, mlp_smem);

    prep_kernel<<<312, 512>>>(wqkv, fc1w, fc2w);
    knn_kernel<<<dim3(NP_ / 16, B_), 512, knn_smem>>>(xyz, nxyz);
    attn_kernel<<<B_ * NP_ / G_, T_, attn_smem>>>(xyz, nxyz, featin, wqkv, projw, projb,
                                                  densew, denseb, n1g, n1b);
    mlp_kernel<<<B_ * NP_ / MR, MT_, mlp_smem>>>(fc1b, fc2b, n2g, n2b, out);
}